// round 12
// baseline (speedup 1.0000x reference)
#include <cuda_runtime.h>
#include <cuda_bf16.h>
#include <math.h>
#include <stdint.h>

// Problem constants
#define PS   16
#define PB   8
#define PL   8
#define PV   32000
#define PD   1024
#define PT   512
#define PG   3
#define SLB  1024
#define D3   3072
#define NTILES 125            // PV / 256 (big-tile logits GEMM)
#define OUT_PTR_ELEMS 32768000LL

// ---------------- device scratch ----------------
__device__ float g_x[SLB * PD];
__device__ float g_h[SLB * PD];
__device__ float g_gi[SLB * D3];
__device__ float g_gh[PB * D3];
__device__ float g_scores[SLB * PT];
__device__ float g_probs[SLB * PT];
__device__ float g_ctx[SLB * PD];
__device__ float g_pgen[SLB];
__device__ float2 g_part2[SLB * NTILES];
__device__ float2 g_rowMS[SLB];
__device__ __nv_bfloat16 g_B2[(long long)PV * 2048];
__device__ __nv_bfloat16 g_A2h[SLB * 2048];
__device__ __nv_bfloat16 g_A2x[SLB * 2048];
__device__ __nv_bfloat16 g_W2[D3 * 2048];
__device__ __nv_bfloat16 g_E2[(long long)PB * PT * 2048];
__device__ __nv_bfloat16 g_ET2[(long long)PB * PD * 1024];
__device__ __nv_bfloat16 g_S2[SLB * 1024];

// ---------------- helpers ----------------
__device__ __forceinline__ uint32_t smem_u32(const void* p) {
    uint32_t a;
    asm("{ .reg .u64 t; cvta.to.shared.u64 t, %1; cvt.u32.u64 %0, t; }" : "=r"(a) : "l"(p));
    return a;
}
__device__ __forceinline__ void cp16(uint32_t s, const void* g) {
    asm volatile("cp.async.cg.shared.global [%0], [%1], 16;" :: "r"(s), "l"(g) : "memory");
}
__device__ __forceinline__ void cp_commit() {
    asm volatile("cp.async.commit_group;" ::: "memory");
}
template <int N>
__device__ __forceinline__ void cp_wait() {
    asm volatile("cp.async.wait_group %0;" :: "n"(N) : "memory");
}
__device__ __forceinline__ void mma16816(float& c0, float& c1, float& c2, float& c3,
                                         uint32_t a0, uint32_t a1, uint32_t a2, uint32_t a3,
                                         uint32_t b0, uint32_t b1) {
    asm volatile("mma.sync.aligned.m16n8k16.row.col.f32.bf16.bf16.f32 "
                 "{%0,%1,%2,%3}, {%4,%5,%6,%7}, {%8,%9}, {%0,%1,%2,%3};"
                 : "+f"(c0), "+f"(c1), "+f"(c2), "+f"(c3)
                 : "r"(a0), "r"(a1), "r"(a2), "r"(a3), "r"(b0), "r"(b1));
}
__device__ __forceinline__ void ldsm4(uint32_t& r0, uint32_t& r1, uint32_t& r2, uint32_t& r3,
                                      uint32_t addr) {
    asm volatile("ldmatrix.sync.aligned.m8n8.x4.shared.b16 {%0,%1,%2,%3}, [%4];"
                 : "=r"(r0), "=r"(r1), "=r"(r2), "=r"(r3) : "r"(addr));
}
__device__ __forceinline__ void split2(float v, __nv_bfloat16& hi, __nv_bfloat16& lo) {
    hi = __float2bfloat16(v);
    lo = __float2bfloat16(v - __bfloat162float(hi));
}
__device__ __forceinline__ uint32_t pack2(float a, float b) {
    __nv_bfloat162 t = __floats2bfloat162_rn(a, b);
    return *reinterpret_cast<uint32_t*>(&t);
}
// truncation-based split of a float pair: hi = top-16-bits (1 PRMT), lo = rn(a - hi)
__device__ __forceinline__ void tsplit_pair(float a, float b, uint32_t& hi, uint32_t& lo) {
    uint32_t ua = __float_as_uint(a), ub = __float_as_uint(b);
    hi = __byte_perm(ua, ub, 0x7632);
    float ha = __uint_as_float(ua & 0xFFFF0000u);
    float hb = __uint_as_float(ub & 0xFFFF0000u);
    lo = pack2(a - ha, b - hb);
}

// ---------------- reductions ----------------
__device__ __forceinline__ float warpMax(float v) {
    #pragma unroll
    for (int o = 16; o; o >>= 1) v = fmaxf(v, __shfl_xor_sync(0xffffffffu, v, o));
    return v;
}
__device__ __forceinline__ float warpSum(float v) {
    #pragma unroll
    for (int o = 16; o; o >>= 1) v += __shfl_xor_sync(0xffffffffu, v, o);
    return v;
}
__device__ float blockSum(float v) {
    __shared__ float sm[32];
    v = warpSum(v);
    int w = threadIdx.x >> 5, l = threadIdx.x & 31;
    __syncthreads();
    if (l == 0) sm[w] = v;
    __syncthreads();
    int nw = (blockDim.x + 31) >> 5;
    v = (threadIdx.x < nw) ? sm[threadIdx.x] : 0.0f;
    if (w == 0) v = warpSum(v);
    if (threadIdx.x == 0) sm[0] = v;
    __syncthreads();
    return sm[0];
}
__device__ float blockMax(float v) {
    __shared__ float sm[32];
    v = warpMax(v);
    int w = threadIdx.x >> 5, l = threadIdx.x & 31;
    __syncthreads();
    if (l == 0) sm[w] = v;
    __syncthreads();
    int nw = (blockDim.x + 31) >> 5;
    v = (threadIdx.x < nw) ? sm[threadIdx.x] : -INFINITY;
    if (w == 0) v = warpMax(v);
    if (threadIdx.x == 0) sm[0] = v;
    __syncthreads();
    return sm[0];
}

// ---------------- split kernels ----------------
// 16 floats (64B) per thread, MLP=4, truncation-split (PRMT hi + rn lo).
// K = 1<<kshift, total16 = nrow * K / 16.
__global__ void split_generic(const float* __restrict__ src, __nv_bfloat16* __restrict__ dst,
                              int kshift, long long total16)
{
    long long idx = (long long)blockIdx.x * 256 + threadIdx.x;
    if (idx >= total16) return;
    long long row = idx >> (kshift - 4);
    int c16 = (int)(idx & ((1 << (kshift - 4)) - 1));
    const float4* s4 = reinterpret_cast<const float4*>(src) + idx * 4;
    float4 v0 = s4[0];
    float4 v1 = s4[1];
    float4 v2 = s4[2];
    float4 v3 = s4[3];
    uint4 uh0, ul0, uh1, ul1;
    tsplit_pair(v0.x, v0.y, uh0.x, ul0.x);
    tsplit_pair(v0.z, v0.w, uh0.y, ul0.y);
    tsplit_pair(v1.x, v1.y, uh0.z, ul0.z);
    tsplit_pair(v1.z, v1.w, uh0.w, ul0.w);
    tsplit_pair(v2.x, v2.y, uh1.x, ul1.x);
    tsplit_pair(v2.z, v2.w, uh1.y, ul1.y);
    tsplit_pair(v3.x, v3.y, uh1.z, ul1.z);
    tsplit_pair(v3.z, v3.w, uh1.w, ul1.w);
    long long K = 1LL << kshift;
    __nv_bfloat16* dh = dst + row * 2 * K + (long long)c16 * 16;
    reinterpret_cast<uint4*>(dh)[0] = uh0;
    reinterpret_cast<uint4*>(dh)[1] = uh1;
    reinterpret_cast<uint4*>(dh + K)[0] = ul0;
    reinterpret_cast<uint4*>(dh + K)[1] = ul1;
}

__global__ void trans_split(const float* __restrict__ enc, __nv_bfloat16* __restrict__ dst)
{
    __shared__ float tile[32][33];
    int b = blockIdx.z;
    int d0 = blockIdx.y * 32;
    int t0 = blockIdx.x * 32;
    int tx = threadIdx.x, ty = threadIdx.y;
    const float* src = enc + ((long long)b * PT + t0) * PD + d0;
    #pragma unroll
    for (int j = 0; j < 4; j++)
        tile[ty + j * 8][tx] = src[(ty + j * 8) * PD + tx];
    __syncthreads();
    #pragma unroll
    for (int j = 0; j < 4; j++) {
        int d = d0 + ty + j * 8;
        float v = tile[tx][ty + j * 8];
        __nv_bfloat16 hi, lo; split2(v, hi, lo);
        long long ro = ((long long)(b << 10) + d) * 1024 + t0 + tx;
        dst[ro] = hi;
        dst[ro + 512] = lo;
    }
}

// ---------------- HMMA split GEMM: 128x128 tile, 4 warps, 2 CTA/SM ----------------
#define STAGE_B 32768
#define MMA_SMEM (3 * STAGE_B)

template <bool ATOMIC>
__global__ void __launch_bounds__(128, 2) mma_gemm(
    const __nv_bfloat16* __restrict__ A2, long long a_rs, long long a_batch,
    const __nv_bfloat16* __restrict__ B2, long long b_rs, long long b_batch,
    float* __restrict__ C, long long c_rs, long long c_batch,
    int Kfull, int ksplit)
{
    extern __shared__ char smd[];
    const uint32_t sbase = smem_u32(smd);
    const int tid = threadIdx.x;
    const int wid = tid >> 5;
    const int lane = tid & 31;
    const int lr = lane >> 2;
    const int mr = (wid & 1) * 64;
    const int nc = (wid >> 1) * 64;
    const long long m0 = (long long)blockIdx.x * 128;
    const long long n0 = (long long)blockIdx.y * 128;
    const int z = blockIdx.z / ksplit;
    const int ks = blockIdx.z % ksplit;
    const int Kp = Kfull / ksplit;
    const int CH = Kp >> 5;
    const int kbase = ks * Kp;
    const __nv_bfloat16* Ab = A2 + (long long)z * a_batch;
    const __nv_bfloat16* Bb = B2 + (long long)z * b_batch;

    const int g3 = lane >> 3;
    const int i8 = lane & 7;
    uint32_t PA[4], PBo[4];
    #pragma unroll
    for (int fm = 0; fm < 4; fm++) {
        uint32_t r = (uint32_t)(mr + fm * 16 + (g3 & 1) * 8 + i8);
        PA[fm] = (r * 64) ^ (((r >> 1) & 3) << 4) ^ ((uint32_t)(g3 >> 1) << 4);
    }
    #pragma unroll
    for (int fn2 = 0; fn2 < 4; fn2++) {
        uint32_t r = (uint32_t)(nc + fn2 * 16 + (g3 >> 1) * 8 + i8);
        PBo[fn2] = (r * 64) ^ (((r >> 1) & 3) << 4) ^ ((uint32_t)(g3 & 1) << 4);
    }

    float acc[4][8][4];
    #pragma unroll
    for (int i = 0; i < 4; i++)
        #pragma unroll
        for (int j = 0; j < 8; j++)
            #pragma unroll
            for (int k = 0; k < 4; k++) acc[i][j][k] = 0.0f;

    auto issue = [&](int c) {
        const int koff = kbase + (c << 5);
        const uint32_t st = sbase + (uint32_t)((c % 3) * STAGE_B);
        #pragma unroll
        for (int i = 0; i < 4; i++) {
            const int idx = tid + i * 128;
            const int r = idx >> 2, g = idx & 3;
            const uint32_t so = (uint32_t)(r * 64 + ((g ^ ((r >> 1) & 3)) << 4));
            const __nv_bfloat16* a = Ab + (m0 + r) * a_rs + koff + g * 8;
            cp16(st + so, a);
            cp16(st + 8192 + so, a + Kfull);
            const __nv_bfloat16* b = Bb + (n0 + r) * b_rs + koff + g * 8;
            cp16(st + 16384 + so, b);
            cp16(st + 24576 + so, b + Kfull);
        }
        cp_commit();
    };

    issue(0); issue(1);

    #pragma unroll 1
    for (int c = 0; c < CH; c++) {
        cp_wait<1>();
        __syncthreads();
        if (c + 2 < CH) issue(c + 2);

        const uint32_t st = sbase + (uint32_t)((c % 3) * STAGE_B);

        #pragma unroll
        for (int kc2 = 0; kc2 < 2; kc2++) {
            const uint32_t kx = (uint32_t)kc2 << 5;
            uint32_t ah[4][4], bh[8][2];
            #pragma unroll
            for (int fm = 0; fm < 4; fm++)
                ldsm4(ah[fm][0], ah[fm][1], ah[fm][2], ah[fm][3], st + (PA[fm] ^ kx));
            #pragma unroll
            for (int fn2 = 0; fn2 < 4; fn2++)
                ldsm4(bh[fn2 * 2][0], bh[fn2 * 2][1], bh[fn2 * 2 + 1][0], bh[fn2 * 2 + 1][1],
                      st + 16384 + (PBo[fn2] ^ kx));
            // pass 1: hi*hi
            #pragma unroll
            for (int fm = 0; fm < 4; fm++)
                #pragma unroll
                for (int fn = 0; fn < 8; fn++)
                    mma16816(acc[fm][fn][0], acc[fm][fn][1], acc[fm][fn][2], acc[fm][fn][3],
                             ah[fm][0], ah[fm][1], ah[fm][2], ah[fm][3], bh[fn][0], bh[fn][1]);
            // pass 2: lo*hi
            {
                uint32_t al[4][4];
                #pragma unroll
                for (int fm = 0; fm < 4; fm++)
                    ldsm4(al[fm][0], al[fm][1], al[fm][2], al[fm][3], st + 8192 + (PA[fm] ^ kx));
                #pragma unroll
                for (int fm = 0; fm < 4; fm++)
                    #pragma unroll
                    for (int fn = 0; fn < 8; fn++)
                        mma16816(acc[fm][fn][0], acc[fm][fn][1], acc[fm][fn][2], acc[fm][fn][3],
                                 al[fm][0], al[fm][1], al[fm][2], al[fm][3], bh[fn][0], bh[fn][1]);
            }
            // pass 3: hi*lo
            {
                uint32_t bl[8][2];
                #pragma unroll
                for (int fn2 = 0; fn2 < 4; fn2++)
                    ldsm4(bl[fn2 * 2][0], bl[fn2 * 2][1], bl[fn2 * 2 + 1][0], bl[fn2 * 2 + 1][1],
                          st + 24576 + (PBo[fn2] ^ kx));
                #pragma unroll
                for (int fm = 0; fm < 4; fm++)
                    #pragma unroll
                    for (int fn = 0; fn < 8; fn++)
                        mma16816(acc[fm][fn][0], acc[fm][fn][1], acc[fm][fn][2], acc[fm][fn][3],
                                 ah[fm][0], ah[fm][1], ah[fm][2], ah[fm][3], bl[fn][0], bl[fn][1]);
            }
        }
    }

    #pragma unroll
    for (int fm = 0; fm < 4; fm++) {
        const int mrow0 = (int)m0 + mr + fm * 16 + lr;
        const int mrow1 = mrow0 + 8;
        long long ro0 = (long long)z * c_batch + (long long)mrow0 * c_rs;
        long long ro1 = (long long)z * c_batch + (long long)mrow1 * c_rs;
        #pragma unroll
        for (int fn = 0; fn < 8; fn++) {
            const long long col = n0 + nc + fn * 8 + (lane & 3) * 2;
            if (ATOMIC) {
                atomicAdd(&C[ro0 + col],     acc[fm][fn][0]);
                atomicAdd(&C[ro0 + col + 1], acc[fm][fn][1]);
                atomicAdd(&C[ro1 + col],     acc[fm][fn][2]);
                atomicAdd(&C[ro1 + col + 1], acc[fm][fn][3]);
            } else {
                *reinterpret_cast<float2*>(C + ro0 + col) = make_float2(acc[fm][fn][0], acc[fm][fn][1]);
                *reinterpret_cast<float2*>(C + ro1 + col) = make_float2(acc[fm][fn][2], acc[fm][fn][3]);
            }
        }
    }
}

// ---------------- logits GEMM: 128x256 tile, 1 CTA/SM, 4-stage ----------------
#define BSTAGE_B 49152
#define BIG_SMEM (4 * BSTAGE_B)

__global__ void __launch_bounds__(256, 1) mma_gemm_big(
    const __nv_bfloat16* __restrict__ A2,   // [SLB][2048]
    const __nv_bfloat16* __restrict__ B2,   // [PV][2048]
    float* __restrict__ C)
{
    extern __shared__ char smd[];
    const uint32_t sbase = smem_u32(smd);
    const int tid = threadIdx.x;
    const int wid = tid >> 5;
    const int lane = tid & 31;
    const int lr = lane >> 2;
    const int mr = (wid & 1) * 64;
    const int nc = (wid >> 1) * 64;
    const long long m0 = (long long)blockIdx.x * 128;
    const long long n0 = (long long)blockIdx.y * 256;

    const int g3 = lane >> 3;
    const int i8 = lane & 7;
    uint32_t PA[4], PBo[4];
    #pragma unroll
    for (int fm = 0; fm < 4; fm++) {
        uint32_t r = (uint32_t)(mr + fm * 16 + (g3 & 1) * 8 + i8);
        PA[fm] = (r * 64) ^ (((r >> 1) & 3) << 4) ^ ((uint32_t)(g3 >> 1) << 4);
    }
    #pragma unroll
    for (int fn2 = 0; fn2 < 4; fn2++) {
        uint32_t r = (uint32_t)(nc + fn2 * 16 + (g3 >> 1) * 8 + i8);
        PBo[fn2] = (r * 64) ^ (((r >> 1) & 3) << 4) ^ ((uint32_t)(g3 & 1) << 4);
    }

    float acc[4][8][4];
    #pragma unroll
    for (int i = 0; i < 4; i++)
        #pragma unroll
        for (int j = 0; j < 8; j++)
            #pragma unroll
            for (int k = 0; k < 4; k++) acc[i][j][k] = 0.0f;

    auto issue = [&](int c) {
        const int koff = c << 5;
        const uint32_t st = sbase + (uint32_t)((c & 3) * BSTAGE_B);
        #pragma unroll
        for (int i = 0; i < 2; i++) {
            const int idx = tid + i * 256;
            const int r = idx >> 2, g = idx & 3;
            const uint32_t so = (uint32_t)(r * 64 + ((g ^ ((r >> 1) & 3)) << 4));
            const __nv_bfloat16* a = A2 + (m0 + r) * 2048 + koff + g * 8;
            cp16(st + so, a);
            cp16(st + 8192 + so, a + 1024);
        }
        #pragma unroll
        for (int i = 0; i < 4; i++) {
            const int idx = tid + i * 256;
            const int r = idx >> 2, g = idx & 3;
            const uint32_t so = (uint32_t)(r * 64 + ((g ^ ((r >> 1) & 3)) << 4));
            const __nv_bfloat16* b = B2 + (n0 + r) * 2048 + koff + g * 8;
            cp16(st + 16384 + so, b);
            cp16(st + 32768 + so, b + 1024);
        }
        cp_commit();
    };

    issue(0); issue(1); issue(2);

    #pragma unroll 1
    for (int c = 0; c < 32; c++) {
        cp_wait<2>();
        __syncthreads();
        if (c + 3 < 32) issue(c + 3);

        const uint32_t st = sbase + (uint32_t)((c & 3) * BSTAGE_B);

        #pragma unroll
        for (int kc2 = 0; kc2 < 2; kc2++) {
            const uint32_t kx = (uint32_t)kc2 << 5;
            uint32_t ah[4][4], bh[8][2];
            #pragma unroll
            for (int fm = 0; fm < 4; fm++)
                ldsm4(ah[fm][0], ah[fm][1], ah[fm][2], ah[fm][3], st + (PA[fm] ^ kx));
            #pragma unroll
            for (int fn2 = 0; fn2 < 4; fn2++)
                ldsm4(bh[fn2 * 2][0], bh[fn2 * 2][1], bh[fn2 * 2 + 1][0], bh[fn2 * 2 + 1][1],
                      st + 16384 + (PBo[fn2] ^ kx));
            // hi * hi
            #pragma unroll
            for (int fm = 0; fm < 4; fm++)
                #pragma unroll
                for (int fn = 0; fn < 8; fn++)
                    mma16816(acc[fm][fn][0], acc[fm][fn][1], acc[fm][fn][2], acc[fm][fn][3],
                             ah[fm][0], ah[fm][1], ah[fm][2], ah[fm][3], bh[fn][0], bh[fn][1]);
            // lo * hi
            {
                uint32_t al[4][4];
                #pragma unroll
                for (int fm = 0; fm < 4; fm++)
                    ldsm4(al[fm][0], al[fm][1], al[fm][2], al[fm][3], st + 8192 + (PA[fm] ^ kx));
                #pragma unroll
                for (int fm = 0; fm < 4; fm++)
                    #pragma unroll
                    for (int fn = 0; fn < 8; fn++)
                        mma16816(acc[fm][fn][0], acc[fm][fn][1], acc[fm][fn][2], acc[fm][fn][3],
                                 al[fm][0], al[fm][1], al[fm][2], al[fm][3], bh[fn][0], bh[fn][1]);
            }
            // hi * lo
            {
                uint32_t bl[8][2];
                #pragma unroll
                for (int fn2 = 0; fn2 < 4; fn2++)
                    ldsm4(bl[fn2 * 2][0], bl[fn2 * 2][1], bl[fn2 * 2 + 1][0], bl[fn2 * 2 + 1][1],
                          st + 32768 + (PBo[fn2] ^ kx));
                #pragma unroll
                for (int fm = 0; fm < 4; fm++)
                    #pragma unroll
                    for (int fn = 0; fn < 8; fn++)
                        mma16816(acc[fm][fn][0], acc[fm][fn][1], acc[fm][fn][2], acc[fm][fn][3],
                                 ah[fm][0], ah[fm][1], ah[fm][2], ah[fm][3], bl[fn][0], bl[fn][1]);
            }
        }
    }

    // store permuted + softmax partials
    #pragma unroll
    for (int fm = 0; fm < 4; fm++) {
        const int mrow0 = (int)m0 + mr + fm * 16 + lr;
        const int mrow1 = mrow0 + 8;
        int s0 = mrow0 >> 6, l0 = (mrow0 >> 3) & 7, b0 = mrow0 & 7;
        int s1 = mrow1 >> 6, l1 = (mrow1 >> 3) & 7, b1 = mrow1 & 7;
        long long ro0 = (long long)((s0 * 8 + b0) * 8 + l0) * (long long)PV;
        long long ro1 = (long long)((s1 * 8 + b1) * 8 + l1) * (long long)PV;
        #pragma unroll
        for (int fn = 0; fn < 8; fn++) {
            const long long col = n0 + nc + fn * 8 + (lane & 3) * 2;
            *reinterpret_cast<float2*>(C + ro0 + col) = make_float2(acc[fm][fn][0], acc[fm][fn][1]);
            *reinterpret_cast<float2*>(C + ro1 + col) = make_float2(acc[fm][fn][2], acc[fm][fn][3]);
        }
    }

    cp_wait<0>();
    __syncthreads();
    float2* part = reinterpret_cast<float2*>(smd);   // [128][4]
    #pragma unroll
    for (int fm = 0; fm < 4; fm++) {
        #pragma unroll
        for (int half = 0; half < 2; half++) {
            float mx = -1e30f;
            #pragma unroll
            for (int fn = 0; fn < 8; fn++)
                mx = fmaxf(mx, fmaxf(acc[fm][fn][half * 2], acc[fm][fn][half * 2 + 1]));
            float se = 0.0f;
            #pragma unroll
            for (int fn = 0; fn < 8; fn++)
                se += __expf(acc[fm][fn][half * 2] - mx)
                    + __expf(acc[fm][fn][half * 2 + 1] - mx);
            #pragma unroll
            for (int off = 1; off <= 2; off <<= 1) {
                float mo = __shfl_xor_sync(0xffffffffu, mx, off);
                float so = __shfl_xor_sync(0xffffffffu, se, off);
                float nm = fmaxf(mx, mo);
                se = se * __expf(mx - nm) + so * __expf(mo - nm);
                mx = nm;
            }
            if ((lane & 3) == 0) {
                int rloc = mr + fm * 16 + lr + half * 8;
                part[rloc * 4 + (wid >> 1)] = make_float2(mx, se);
            }
        }
    }
    __syncthreads();
    if (tid < 128) {
        float2 p0 = part[tid * 4 + 0];
        float2 p1 = part[tid * 4 + 1];
        float2 p2 = part[tid * 4 + 2];
        float2 p3 = part[tid * 4 + 3];
        float M = fmaxf(fmaxf(p0.x, p1.x), fmaxf(p2.x, p3.x));
        float S = p0.y * __expf(p0.x - M) + p1.y * __expf(p1.x - M)
                + p2.y * __expf(p2.x - M) + p3.y * __expf(p3.x - M);
        int mrow = (int)m0 + tid;
        int s = mrow >> 6, l = (mrow >> 3) & 7, b = mrow & 7;
        int o = (s * 8 + b) * 8 + l;
        g_part2[o * NTILES + blockIdx.y] = make_float2(M, S);
    }
}

// ---------------- small kernels ----------------
__global__ void gh_kernel(const float* __restrict__ h0, const float* __restrict__ whh,
                          const float* __restrict__ bhh)
{
    int i = blockIdx.x * 256 + threadIdx.x;
    if (i >= PB * D3) return;
    int b = i / D3, e = i % D3;
    float acc = bhh[e];
    const float4* hr = reinterpret_cast<const float4*>(h0 + b * PD);
    const float4* wr = reinterpret_cast<const float4*>(whh + (long long)e * PD);
    #pragma unroll 4
    for (int k = 0; k < PD / 4; k++) {
        float4 a = hr[k], w = wr[k];
        acc = fmaf(a.x, w.x, acc); acc = fmaf(a.y, w.y, acc);
        acc = fmaf(a.z, w.z, acc); acc = fmaf(a.w, w.w, acc);
    }
    g_gh[i] = acc;
}

__global__ void build_x(const float* __restrict__ emb, const float* __restrict__ slot,
                        const int* __restrict__ trg)
{
    int idx = blockIdx.x * 256 + threadIdx.x;
    int d = idx & (PD - 1);
    int m = idx >> 10;
    int s = m >> 6, l = (m >> 3) & 7, b = m & 7;
    float v;
    if (l == 0) v = slot[s * PD + d];
    else {
        int tok = trg[b * (PS * PL) + s * PL + (l - 1)];
        v = emb[(long long)tok * PD + d];
    }
    g_x[idx] = v;
    __nv_bfloat16 hi, lo; split2(v, hi, lo);
    g_A2x[m * 2048 + d] = hi;
    g_A2x[m * 2048 + 1024 + d] = lo;
}

__global__ void gru_kernel(const float* __restrict__ bih, const float* __restrict__ h0)
{
    int idx = blockIdx.x * 256 + threadIdx.x;
    int d = idx & (PD - 1);
    int m = idx >> 10;
    int b = m & 7;
    long long gb = (long long)m * D3;
    float ir = g_gi[gb + d]          + bih[d];
    float iz = g_gi[gb + PD + d]     + bih[PD + d];
    float in = g_gi[gb + 2 * PD + d] + bih[2 * PD + d];
    float hr = g_gh[b * D3 + d];
    float hz = g_gh[b * D3 + PD + d];
    float hn = g_gh[b * D3 + 2 * PD + d];
    float r = 1.0f / (1.0f + expf(-(ir + hr)));
    float z = 1.0f / (1.0f + expf(-(iz + hz)));
    float n = tanhf(in + r * hn);
    float h = (1.0f - z) * n + z * h0[b * PD + d];
    g_h[idx] = h;
    __nv_bfloat16 hi, lo; split2(h, hi, lo);
    g_A2h[m * 2048 + d] = hi;
    g_A2h[m * 2048 + 1024 + d] = lo;
}

__global__ void probs_kernel()
{
    int m = blockIdx.x;
    long long base = (long long)m * PT;
    int t = threadIdx.x;
    float v0 = g_scores[base + t];
    float v1 = g_scores[base + t + 256];
    float mx = blockMax(fmaxf(v0, v1));
    float e0 = __expf(v0 - mx), e1 = __expf(v1 - mx);
    float sum = blockSum(e0 + e1);
    float inv = 1.0f / sum;
    g_probs[base + t] = e0 * inv;
    g_probs[base + t + 256] = e1 * inv;
    __nv_bfloat16 h, lo;
    split2(v0, h, lo);
    g_S2[m * 1024 + t] = h; g_S2[m * 1024 + 512 + t] = lo;
    split2(v1, h, lo);
    g_S2[m * 1024 + t + 256] = h; g_S2[m * 1024 + 512 + t + 256] = lo;
}

__global__ void pgen_kernel(const float* __restrict__ w, const float* __restrict__ wb)
{
    int m = blockIdx.x;
    long long base = (long long)m * PD;
    float p = 0.0f;
    for (int d = threadIdx.x; d < PD; d += 256) {
        p = fmaf(g_h[base + d],   w[d],          p);
        p = fmaf(g_ctx[base + d], w[PD + d],     p);
        p = fmaf(g_x[base + d],   w[2 * PD + d], p);
    }
    p = blockSum(p);
    if (threadIdx.x == 0)
        g_pgen[m] = 1.0f / (1.0f + expf(-(p + wb[0])));
}

__global__ void combine_kernel()
{
    int o = blockIdx.x;
    int i = threadIdx.x;
    float M = -1e30f, S = 0.0f;
    if (i < NTILES) {
        float2 p = g_part2[o * NTILES + i];
        M = p.x; S = p.y;
    }
    __shared__ float smx[128], ssm[128];
    smx[i] = M; ssm[i] = S;
    __syncthreads();
    for (int st = 64; st; st >>= 1) {
        if (i < st) {
            float m1 = smx[i], s1 = ssm[i];
            float m2 = smx[i + st], s2 = ssm[i + st];
            float nm = fmaxf(m1, m2);
            smx[i] = nm;
            ssm[i] = s1 * __expf(m1 - nm) + s2 * __expf(m2 - nm);
        }
        __syncthreads();
    }
    if (i == 0) {
        int s = o >> 6, b = (o >> 3) & 7, l = o & 7;
        int m = s * 64 + l * 8 + b;
        float pg = g_pgen[m];
        g_rowMS[o] = make_float2(smx[0], pg / ssm[0]);
    }
}

__global__ void final_kernel(float* __restrict__ out, const int* __restrict__ story)
{
    int o = blockIdx.x;
    float2 ms = g_rowMS[o];
    long long base = (long long)o * PV;
    int s = o >> 6, b = (o >> 3) & 7, l = o & 7;
    int m = s * 64 + l * 8 + b;
    float4* dst = reinterpret_cast<float4*>(out + base);
    for (int i = threadIdx.x; i < PV / 4; i += 256) {
        float4 v = dst[i];
        v.x = __expf(v.x - ms.x) * ms.y;
        v.y = __expf(v.y - ms.x) * ms.y;
        v.z = __expf(v.z - ms.x) * ms.y;
        v.w = __expf(v.w - ms.x) * ms.y;
        dst[i] = v;
    }
    __syncthreads();
    float w = 1.0f - g_pgen[m];
    for (int t = threadIdx.x; t < PT; t += 256) {
        int tok = story[b * PT + t];
        atomicAdd(&out[base + tok], w * g_probs[(long long)m * PT + t]);
    }
}

__global__ void gate_kernel(float* __restrict__ out, const float* __restrict__ wg,
                            const float* __restrict__ bg)
{
    int o = blockIdx.x;
    int s = o / (PB * PG);
    int b = (o % (PB * PG)) / PG;
    int g = o % PG;
    int m = s * 64 + b;
    float p = 0.0f;
    for (int d = threadIdx.x; d < PD; d += 128)
        p = fmaf(g_ctx[(long long)m * PD + d], wg[g * PD + d], p);
    p = blockSum(p);
    if (threadIdx.x == 0) out[OUT_PTR_ELEMS + o] = p + bg[g];
}

// ---------------- launch ----------------
extern "C" void kernel_launch(void* const* d_in, const int* in_sizes, int n_in,
                              void* d_out, int out_size)
{
    const float* enc_h   = (const float*)d_in[0];
    const float* enc_out = (const float*)d_in[1];
    const int*   story   = (const int*)d_in[2];
    const int*   trg     = (const int*)d_in[3];
    const float* emb     = (const float*)d_in[4];
    const float* w_ih    = (const float*)d_in[5];
    const float* w_hh    = (const float*)d_in[6];
    const float* b_ih    = (const float*)d_in[7];
    const float* b_hh    = (const float*)d_in[8];
    const float* w_rw    = (const float*)d_in[9];
    const float* w_rb    = (const float*)d_in[10];
    const float* w_gw    = (const float*)d_in[11];
    const float* w_gb    = (const float*)d_in[12];
    const float* slot    = (const float*)d_in[13];
    float* out = (float*)d_out;

    float *pgi, *psc, *pcx;
    __nv_bfloat16 *pB2, *pA2h, *pA2x, *pW2, *pE2, *pET2, *pS2;
    cudaGetSymbolAddress((void**)&pgi,  g_gi);
    cudaGetSymbolAddress((void**)&psc,  g_scores);
    cudaGetSymbolAddress((void**)&pcx,  g_ctx);
    cudaGetSymbolAddress((void**)&pB2,  g_B2);
    cudaGetSymbolAddress((void**)&pA2h, g_A2h);
    cudaGetSymbolAddress((void**)&pA2x, g_A2x);
    cudaGetSymbolAddress((void**)&pW2,  g_W2);
    cudaGetSymbolAddress((void**)&pE2,  g_E2);
    cudaGetSymbolAddress((void**)&pET2, g_ET2);
    cudaGetSymbolAddress((void**)&pS2,  g_S2);

    cudaFuncSetAttribute(mma_gemm<false>, cudaFuncAttributeMaxDynamicSharedMemorySize, MMA_SMEM);
    cudaFuncSetAttribute(mma_gemm<true>,  cudaFuncAttributeMaxDynamicSharedMemorySize, MMA_SMEM);
    cudaFuncSetAttribute(mma_gemm_big,    cudaFuncAttributeMaxDynamicSharedMemorySize, BIG_SMEM);

    // zero split-K accumulation targets
    cudaMemsetAsync(pgi, 0, (size_t)SLB * D3 * 4);
    cudaMemsetAsync(psc, 0, (size_t)SLB * PT * 4);
    cudaMemsetAsync(pcx, 0, (size_t)SLB * PD * 4);

    // inputs + operand splits (fast truncation split, 64B/thread)
    build_x<<<(SLB * PD) / 256, 256>>>(emb, slot, trg);
    split_generic<<<D3 * 64 / 256, 256>>>(w_ih, pW2, 10, (long long)D3 * 64);
    split_generic<<<PV * 64 / 256, 256>>>(emb, pB2, 10, (long long)PV * 64);

    // gi = x @ w_ih^T (M=1024, N=3072, K=1024), split-K=2
    mma_gemm<true><<<dim3(8, 24, 2), 128, MMA_SMEM>>>(
        pA2x, 2048, 0, pW2, 2048, 0, pgi, D3, 0, 1024, 2);

    // enc splits + gh
    split_generic<<<PB * PT * 64 / 256, 256>>>(enc_out, pE2, 10, (long long)PB * PT * 64);
    trans_split<<<dim3(PT / 32, PD / 32, PB), dim3(32, 8)>>>(enc_out, pET2);
    gh_kernel<<<(PB * D3 + 255) / 256, 256>>>(enc_h, w_hh, b_hh);

    // GRU -> h (+ split)
    gru_kernel<<<(SLB * PD) / 256, 256>>>(b_ih, enc_h);

    // scores = h . enc (per-b M=128, N=512, K=1024), split-K=4
    mma_gemm<true><<<dim3(1, 4, 32), 128, MMA_SMEM>>>(
        pA2h, 8 * 2048, 2048, pE2, 2048, (long long)PT * 2048,
        psc, 8 * 512, 512, 1024, 4);

    // probs (+ S2 split)
    probs_kernel<<<SLB, 256>>>();

    // context = scores @ enc (per-b M=128, N=1024, K=512), split-K=4
    mma_gemm<true><<<dim3(1, 8, 32), 128, MMA_SMEM>>>(
        pS2, 8 * 1024, 1024, pET2, 1024, (long long)PD * 1024,
        pcx, 8 * 1024, 1024, 512, 4);

    // p_gen
    pgen_kernel<<<SLB, 256>>>(w_rw, w_rb);

    // logits = h @ E^T (M=1024, N=32000, K=1024), 128x256 tiles, 4-stage
    mma_gemm_big<<<dim3(8, NTILES), 256, BIG_SMEM>>>(pA2h, pB2, out);

    // combine partials -> per-row (M, pg/S)
    combine_kernel<<<SLB, 128>>>();

    // scale + scatter
    final_kernel<<<SLB, 256>>>(out, story);

    // gate outputs
    gate_kernel<<<PS * PB * PG, 128>>>(out, w_gw, w_gb);
}

// round 14
// speedup vs baseline: 1.5013x; 1.5013x over previous
#include <cuda_runtime.h>
#include <cuda_bf16.h>
#include <math.h>
#include <stdint.h>

// Problem constants
#define PS   16
#define PB   8
#define PL   8
#define PV   32000
#define PD   1024
#define PT   512
#define PG   3
#define SLB  1024
#define D3   3072
#define NTILES 125            // PV / 256 (big-tile logits GEMM)
#define OUT_PTR_ELEMS 32768000LL

// ---------------- device scratch ----------------
__device__ float g_x[SLB * PD];
__device__ float g_h[SLB * PD];
__device__ float g_gi[SLB * D3];
__device__ float g_gh[PB * D3];
__device__ float g_scores[SLB * PT];
__device__ float g_probs[SLB * PT];
__device__ float g_ctx[SLB * PD];
__device__ float g_pgen[SLB];
__device__ float2 g_part2[SLB * NTILES];
__device__ float2 g_rowMS[SLB];
__device__ __nv_bfloat16 g_B2[(long long)PV * 2048];
__device__ __nv_bfloat16 g_A2h[SLB * 2048];
__device__ __nv_bfloat16 g_A2x[SLB * 2048];
__device__ __nv_bfloat16 g_W2[D3 * 2048];
__device__ __nv_bfloat16 g_E2[(long long)PB * PT * 2048];
__device__ __nv_bfloat16 g_ET2[(long long)PB * PD * 1024];
__device__ __nv_bfloat16 g_S2[SLB * 1024];

// ---------------- helpers ----------------
__device__ __forceinline__ uint32_t smem_u32(const void* p) {
    uint32_t a;
    asm("{ .reg .u64 t; cvta.to.shared.u64 t, %1; cvt.u32.u64 %0, t; }" : "=r"(a) : "l"(p));
    return a;
}
__device__ __forceinline__ void cp16(uint32_t s, const void* g) {
    asm volatile("cp.async.cg.shared.global [%0], [%1], 16;" :: "r"(s), "l"(g) : "memory");
}
__device__ __forceinline__ void cp_commit() {
    asm volatile("cp.async.commit_group;" ::: "memory");
}
template <int N>
__device__ __forceinline__ void cp_wait() {
    asm volatile("cp.async.wait_group %0;" :: "n"(N) : "memory");
}
__device__ __forceinline__ void mma16816(float& c0, float& c1, float& c2, float& c3,
                                         uint32_t a0, uint32_t a1, uint32_t a2, uint32_t a3,
                                         uint32_t b0, uint32_t b1) {
    asm volatile("mma.sync.aligned.m16n8k16.row.col.f32.bf16.bf16.f32 "
                 "{%0,%1,%2,%3}, {%4,%5,%6,%7}, {%8,%9}, {%0,%1,%2,%3};"
                 : "+f"(c0), "+f"(c1), "+f"(c2), "+f"(c3)
                 : "r"(a0), "r"(a1), "r"(a2), "r"(a3), "r"(b0), "r"(b1));
}
__device__ __forceinline__ void ldsm4(uint32_t& r0, uint32_t& r1, uint32_t& r2, uint32_t& r3,
                                      uint32_t addr) {
    asm volatile("ldmatrix.sync.aligned.m8n8.x4.shared.b16 {%0,%1,%2,%3}, [%4];"
                 : "=r"(r0), "=r"(r1), "=r"(r2), "=r"(r3) : "r"(addr));
}
__device__ __forceinline__ void split2(float v, __nv_bfloat16& hi, __nv_bfloat16& lo) {
    hi = __float2bfloat16(v);
    lo = __float2bfloat16(v - __bfloat162float(hi));
}
__device__ __forceinline__ uint32_t pack2(float a, float b) {
    __nv_bfloat162 t = __floats2bfloat162_rn(a, b);
    return *reinterpret_cast<uint32_t*>(&t);
}

// ---------------- reductions ----------------
__device__ __forceinline__ float warpMax(float v) {
    #pragma unroll
    for (int o = 16; o; o >>= 1) v = fmaxf(v, __shfl_xor_sync(0xffffffffu, v, o));
    return v;
}
__device__ __forceinline__ float warpSum(float v) {
    #pragma unroll
    for (int o = 16; o; o >>= 1) v += __shfl_xor_sync(0xffffffffu, v, o);
    return v;
}
__device__ float blockSum(float v) {
    __shared__ float sm[32];
    v = warpSum(v);
    int w = threadIdx.x >> 5, l = threadIdx.x & 31;
    __syncthreads();
    if (l == 0) sm[w] = v;
    __syncthreads();
    int nw = (blockDim.x + 31) >> 5;
    v = (threadIdx.x < nw) ? sm[threadIdx.x] : 0.0f;
    if (w == 0) v = warpSum(v);
    if (threadIdx.x == 0) sm[0] = v;
    __syncthreads();
    return sm[0];
}
__device__ float blockMax(float v) {
    __shared__ float sm[32];
    v = warpMax(v);
    int w = threadIdx.x >> 5, l = threadIdx.x & 31;
    __syncthreads();
    if (l == 0) sm[w] = v;
    __syncthreads();
    int nw = (blockDim.x + 31) >> 5;
    v = (threadIdx.x < nw) ? sm[threadIdx.x] : -INFINITY;
    if (w == 0) v = warpMax(v);
    if (threadIdx.x == 0) sm[0] = v;
    __syncthreads();
    return sm[0];
}

// ---------------- split kernels ----------------
// 8 floats per thread, rounding-based split (validated numerics).
__global__ void split_generic(const float* __restrict__ src, __nv_bfloat16* __restrict__ dst,
                              int kshift, long long total8)
{
    long long idx = (long long)blockIdx.x * 256 + threadIdx.x;
    if (idx >= total8) return;
    long long row = idx >> (kshift - 3);
    int c8 = (int)(idx & ((1 << (kshift - 3)) - 1));
    const float4* s4 = reinterpret_cast<const float4*>(src);
    float4 v0 = s4[idx * 2];
    float4 v1 = s4[idx * 2 + 1];
    uint4 uh, ul;
    uh.x = pack2(v0.x, v0.y);
    uh.y = pack2(v0.z, v0.w);
    uh.z = pack2(v1.x, v1.y);
    uh.w = pack2(v1.z, v1.w);
    float2 f;
    __nv_bfloat162 t;
    t = *reinterpret_cast<__nv_bfloat162*>(&uh.x); f = __bfloat1622float2(t);
    ul.x = pack2(v0.x - f.x, v0.y - f.y);
    t = *reinterpret_cast<__nv_bfloat162*>(&uh.y); f = __bfloat1622float2(t);
    ul.y = pack2(v0.z - f.x, v0.w - f.y);
    t = *reinterpret_cast<__nv_bfloat162*>(&uh.z); f = __bfloat1622float2(t);
    ul.z = pack2(v1.x - f.x, v1.y - f.y);
    t = *reinterpret_cast<__nv_bfloat162*>(&uh.w); f = __bfloat1622float2(t);
    ul.w = pack2(v1.z - f.x, v1.w - f.y);
    long long K = 1LL << kshift;
    __nv_bfloat16* dh = dst + row * 2 * K + (long long)c8 * 8;
    *reinterpret_cast<uint4*>(dh) = uh;
    *reinterpret_cast<uint4*>(dh + K) = ul;
}

__global__ void trans_split(const float* __restrict__ enc, __nv_bfloat16* __restrict__ dst)
{
    __shared__ float tile[32][33];
    int b = blockIdx.z;
    int d0 = blockIdx.y * 32;
    int t0 = blockIdx.x * 32;
    int tx = threadIdx.x, ty = threadIdx.y;
    const float* src = enc + ((long long)b * PT + t0) * PD + d0;
    #pragma unroll
    for (int j = 0; j < 4; j++)
        tile[ty + j * 8][tx] = src[(ty + j * 8) * PD + tx];
    __syncthreads();
    #pragma unroll
    for (int j = 0; j < 4; j++) {
        int d = d0 + ty + j * 8;
        float v = tile[tx][ty + j * 8];
        __nv_bfloat16 hi, lo; split2(v, hi, lo);
        long long ro = ((long long)(b << 10) + d) * 1024 + t0 + tx;
        dst[ro] = hi;
        dst[ro + 512] = lo;
    }
}

// ---------------- HMMA split GEMM: 128x128 tile, 4 warps, 2 CTA/SM ----------------
#define STAGE_B 32768
#define MMA_SMEM (3 * STAGE_B)

template <bool ATOMIC>
__global__ void __launch_bounds__(128, 2) mma_gemm(
    const __nv_bfloat16* __restrict__ A2, long long a_rs, long long a_batch,
    const __nv_bfloat16* __restrict__ B2, long long b_rs, long long b_batch,
    float* __restrict__ C, long long c_rs, long long c_batch,
    int Kfull, int ksplit)
{
    extern __shared__ char smd[];
    const uint32_t sbase = smem_u32(smd);
    const int tid = threadIdx.x;
    const int wid = tid >> 5;
    const int lane = tid & 31;
    const int lr = lane >> 2;
    const int mr = (wid & 1) * 64;
    const int nc = (wid >> 1) * 64;
    const long long m0 = (long long)blockIdx.x * 128;
    const long long n0 = (long long)blockIdx.y * 128;
    const int z = blockIdx.z / ksplit;
    const int ks = blockIdx.z % ksplit;
    const int Kp = Kfull / ksplit;
    const int CH = Kp >> 5;
    const int kbase = ks * Kp;
    const __nv_bfloat16* Ab = A2 + (long long)z * a_batch;
    const __nv_bfloat16* Bb = B2 + (long long)z * b_batch;

    const int g3 = lane >> 3;
    const int i8 = lane & 7;
    uint32_t PA[4], PBo[4];
    #pragma unroll
    for (int fm = 0; fm < 4; fm++) {
        uint32_t r = (uint32_t)(mr + fm * 16 + (g3 & 1) * 8 + i8);
        PA[fm] = (r * 64) ^ (((r >> 1) & 3) << 4) ^ ((uint32_t)(g3 >> 1) << 4);
    }
    #pragma unroll
    for (int fn2 = 0; fn2 < 4; fn2++) {
        uint32_t r = (uint32_t)(nc + fn2 * 16 + (g3 >> 1) * 8 + i8);
        PBo[fn2] = (r * 64) ^ (((r >> 1) & 3) << 4) ^ ((uint32_t)(g3 & 1) << 4);
    }

    float acc[4][8][4];
    #pragma unroll
    for (int i = 0; i < 4; i++)
        #pragma unroll
        for (int j = 0; j < 8; j++)
            #pragma unroll
            for (int k = 0; k < 4; k++) acc[i][j][k] = 0.0f;

    auto issue = [&](int c) {
        const int koff = kbase + (c << 5);
        const uint32_t st = sbase + (uint32_t)((c % 3) * STAGE_B);
        #pragma unroll
        for (int i = 0; i < 4; i++) {
            const int idx = tid + i * 128;
            const int r = idx >> 2, g = idx & 3;
            const uint32_t so = (uint32_t)(r * 64 + ((g ^ ((r >> 1) & 3)) << 4));
            const __nv_bfloat16* a = Ab + (m0 + r) * a_rs + koff + g * 8;
            cp16(st + so, a);
            cp16(st + 8192 + so, a + Kfull);
            const __nv_bfloat16* b = Bb + (n0 + r) * b_rs + koff + g * 8;
            cp16(st + 16384 + so, b);
            cp16(st + 24576 + so, b + Kfull);
        }
        cp_commit();
    };

    issue(0); issue(1);

    #pragma unroll 1
    for (int c = 0; c < CH; c++) {
        cp_wait<1>();
        __syncthreads();
        if (c + 2 < CH) issue(c + 2);

        const uint32_t st = sbase + (uint32_t)((c % 3) * STAGE_B);

        #pragma unroll
        for (int kc2 = 0; kc2 < 2; kc2++) {
            const uint32_t kx = (uint32_t)kc2 << 5;
            uint32_t ah[4][4], bh[8][2];
            #pragma unroll
            for (int fm = 0; fm < 4; fm++)
                ldsm4(ah[fm][0], ah[fm][1], ah[fm][2], ah[fm][3], st + (PA[fm] ^ kx));
            #pragma unroll
            for (int fn2 = 0; fn2 < 4; fn2++)
                ldsm4(bh[fn2 * 2][0], bh[fn2 * 2][1], bh[fn2 * 2 + 1][0], bh[fn2 * 2 + 1][1],
                      st + 16384 + (PBo[fn2] ^ kx));
            // pass 1: hi*hi
            #pragma unroll
            for (int fm = 0; fm < 4; fm++)
                #pragma unroll
                for (int fn = 0; fn < 8; fn++)
                    mma16816(acc[fm][fn][0], acc[fm][fn][1], acc[fm][fn][2], acc[fm][fn][3],
                             ah[fm][0], ah[fm][1], ah[fm][2], ah[fm][3], bh[fn][0], bh[fn][1]);
            // pass 2: lo*hi
            {
                uint32_t al[4][4];
                #pragma unroll
                for (int fm = 0; fm < 4; fm++)
                    ldsm4(al[fm][0], al[fm][1], al[fm][2], al[fm][3], st + 8192 + (PA[fm] ^ kx));
                #pragma unroll
                for (int fm = 0; fm < 4; fm++)
                    #pragma unroll
                    for (int fn = 0; fn < 8; fn++)
                        mma16816(acc[fm][fn][0], acc[fm][fn][1], acc[fm][fn][2], acc[fm][fn][3],
                                 al[fm][0], al[fm][1], al[fm][2], al[fm][3], bh[fn][0], bh[fn][1]);
            }
            // pass 3: hi*lo
            {
                uint32_t bl[8][2];
                #pragma unroll
                for (int fn2 = 0; fn2 < 4; fn2++)
                    ldsm4(bl[fn2 * 2][0], bl[fn2 * 2][1], bl[fn2 * 2 + 1][0], bl[fn2 * 2 + 1][1],
                          st + 24576 + (PBo[fn2] ^ kx));
                #pragma unroll
                for (int fm = 0; fm < 4; fm++)
                    #pragma unroll
                    for (int fn = 0; fn < 8; fn++)
                        mma16816(acc[fm][fn][0], acc[fm][fn][1], acc[fm][fn][2], acc[fm][fn][3],
                                 ah[fm][0], ah[fm][1], ah[fm][2], ah[fm][3], bl[fn][0], bl[fn][1]);
            }
        }
    }

    #pragma unroll
    for (int fm = 0; fm < 4; fm++) {
        const int mrow0 = (int)m0 + mr + fm * 16 + lr;
        const int mrow1 = mrow0 + 8;
        long long ro0 = (long long)z * c_batch + (long long)mrow0 * c_rs;
        long long ro1 = (long long)z * c_batch + (long long)mrow1 * c_rs;
        #pragma unroll
        for (int fn = 0; fn < 8; fn++) {
            const long long col = n0 + nc + fn * 8 + (lane & 3) * 2;
            if (ATOMIC) {
                atomicAdd(&C[ro0 + col],     acc[fm][fn][0]);
                atomicAdd(&C[ro0 + col + 1], acc[fm][fn][1]);
                atomicAdd(&C[ro1 + col],     acc[fm][fn][2]);
                atomicAdd(&C[ro1 + col + 1], acc[fm][fn][3]);
            } else {
                *reinterpret_cast<float2*>(C + ro0 + col) = make_float2(acc[fm][fn][0], acc[fm][fn][1]);
                *reinterpret_cast<float2*>(C + ro1 + col) = make_float2(acc[fm][fn][2], acc[fm][fn][3]);
            }
        }
    }
}

// ---------------- logits GEMM: 128x256 tile, 1 CTA/SM, 4-stage ----------------
#define BSTAGE_B 49152
#define BIG_SMEM (4 * BSTAGE_B)

__global__ void __launch_bounds__(256, 1) mma_gemm_big(
    const __nv_bfloat16* __restrict__ A2,   // [SLB][2048]
    const __nv_bfloat16* __restrict__ B2,   // [PV][2048]
    float* __restrict__ C)
{
    extern __shared__ char smd[];
    const uint32_t sbase = smem_u32(smd);
    const int tid = threadIdx.x;
    const int wid = tid >> 5;
    const int lane = tid & 31;
    const int lr = lane >> 2;
    const int mr = (wid & 1) * 64;
    const int nc = (wid >> 1) * 64;
    const long long m0 = (long long)blockIdx.x * 128;
    const long long n0 = (long long)blockIdx.y * 256;

    const int g3 = lane >> 3;
    const int i8 = lane & 7;
    uint32_t PA[4], PBo[4];
    #pragma unroll
    for (int fm = 0; fm < 4; fm++) {
        uint32_t r = (uint32_t)(mr + fm * 16 + (g3 & 1) * 8 + i8);
        PA[fm] = (r * 64) ^ (((r >> 1) & 3) << 4) ^ ((uint32_t)(g3 >> 1) << 4);
    }
    #pragma unroll
    for (int fn2 = 0; fn2 < 4; fn2++) {
        uint32_t r = (uint32_t)(nc + fn2 * 16 + (g3 >> 1) * 8 + i8);
        PBo[fn2] = (r * 64) ^ (((r >> 1) & 3) << 4) ^ ((uint32_t)(g3 & 1) << 4);
    }

    float acc[4][8][4];
    #pragma unroll
    for (int i = 0; i < 4; i++)
        #pragma unroll
        for (int j = 0; j < 8; j++)
            #pragma unroll
            for (int k = 0; k < 4; k++) acc[i][j][k] = 0.0f;

    auto issue = [&](int c) {
        const int koff = c << 5;
        const uint32_t st = sbase + (uint32_t)((c & 3) * BSTAGE_B);
        #pragma unroll
        for (int i = 0; i < 2; i++) {
            const int idx = tid + i * 256;
            const int r = idx >> 2, g = idx & 3;
            const uint32_t so = (uint32_t)(r * 64 + ((g ^ ((r >> 1) & 3)) << 4));
            const __nv_bfloat16* a = A2 + (m0 + r) * 2048 + koff + g * 8;
            cp16(st + so, a);
            cp16(st + 8192 + so, a + 1024);
        }
        #pragma unroll
        for (int i = 0; i < 4; i++) {
            const int idx = tid + i * 256;
            const int r = idx >> 2, g = idx & 3;
            const uint32_t so = (uint32_t)(r * 64 + ((g ^ ((r >> 1) & 3)) << 4));
            const __nv_bfloat16* b = B2 + (n0 + r) * 2048 + koff + g * 8;
            cp16(st + 16384 + so, b);
            cp16(st + 32768 + so, b + 1024);
        }
        cp_commit();
    };

    issue(0); issue(1); issue(2);

    #pragma unroll 1
    for (int c = 0; c < 32; c++) {
        cp_wait<2>();
        __syncthreads();
        if (c + 3 < 32) issue(c + 3);

        const uint32_t st = sbase + (uint32_t)((c & 3) * BSTAGE_B);

        #pragma unroll
        for (int kc2 = 0; kc2 < 2; kc2++) {
            const uint32_t kx = (uint32_t)kc2 << 5;
            uint32_t ah[4][4], bh[8][2];
            #pragma unroll
            for (int fm = 0; fm < 4; fm++)
                ldsm4(ah[fm][0], ah[fm][1], ah[fm][2], ah[fm][3], st + (PA[fm] ^ kx));
            #pragma unroll
            for (int fn2 = 0; fn2 < 4; fn2++)
                ldsm4(bh[fn2 * 2][0], bh[fn2 * 2][1], bh[fn2 * 2 + 1][0], bh[fn2 * 2 + 1][1],
                      st + 16384 + (PBo[fn2] ^ kx));
            // hi * hi
            #pragma unroll
            for (int fm = 0; fm < 4; fm++)
                #pragma unroll
                for (int fn = 0; fn < 8; fn++)
                    mma16816(acc[fm][fn][0], acc[fm][fn][1], acc[fm][fn][2], acc[fm][fn][3],
                             ah[fm][0], ah[fm][1], ah[fm][2], ah[fm][3], bh[fn][0], bh[fn][1]);
            // lo * hi
            {
                uint32_t al[4][4];
                #pragma unroll
                for (int fm = 0; fm < 4; fm++)
                    ldsm4(al[fm][0], al[fm][1], al[fm][2], al[fm][3], st + 8192 + (PA[fm] ^ kx));
                #pragma unroll
                for (int fm = 0; fm < 4; fm++)
                    #pragma unroll
                    for (int fn = 0; fn < 8; fn++)
                        mma16816(acc[fm][fn][0], acc[fm][fn][1], acc[fm][fn][2], acc[fm][fn][3],
                                 al[fm][0], al[fm][1], al[fm][2], al[fm][3], bh[fn][0], bh[fn][1]);
            }
            // hi * lo
            {
                uint32_t bl[8][2];
                #pragma unroll
                for (int fn2 = 0; fn2 < 4; fn2++)
                    ldsm4(bl[fn2 * 2][0], bl[fn2 * 2][1], bl[fn2 * 2 + 1][0], bl[fn2 * 2 + 1][1],
                          st + 32768 + (PBo[fn2] ^ kx));
                #pragma unroll
                for (int fm = 0; fm < 4; fm++)
                    #pragma unroll
                    for (int fn = 0; fn < 8; fn++)
                        mma16816(acc[fm][fn][0], acc[fm][fn][1], acc[fm][fn][2], acc[fm][fn][3],
                                 ah[fm][0], ah[fm][1], ah[fm][2], ah[fm][3], bl[fn][0], bl[fn][1]);
            }
        }
    }

    // store permuted + softmax partials
    #pragma unroll
    for (int fm = 0; fm < 4; fm++) {
        const int mrow0 = (int)m0 + mr + fm * 16 + lr;
        const int mrow1 = mrow0 + 8;
        int s0 = mrow0 >> 6, l0 = (mrow0 >> 3) & 7, b0 = mrow0 & 7;
        int s1 = mrow1 >> 6, l1 = (mrow1 >> 3) & 7, b1 = mrow1 & 7;
        long long ro0 = (long long)((s0 * 8 + b0) * 8 + l0) * (long long)PV;
        long long ro1 = (long long)((s1 * 8 + b1) * 8 + l1) * (long long)PV;
        #pragma unroll
        for (int fn = 0; fn < 8; fn++) {
            const long long col = n0 + nc + fn * 8 + (lane & 3) * 2;
            *reinterpret_cast<float2*>(C + ro0 + col) = make_float2(acc[fm][fn][0], acc[fm][fn][1]);
            *reinterpret_cast<float2*>(C + ro1 + col) = make_float2(acc[fm][fn][2], acc[fm][fn][3]);
        }
    }

    cp_wait<0>();
    __syncthreads();
    float2* part = reinterpret_cast<float2*>(smd);   // [128][4]
    #pragma unroll
    for (int fm = 0; fm < 4; fm++) {
        #pragma unroll
        for (int half = 0; half < 2; half++) {
            float mx = -1e30f;
            #pragma unroll
            for (int fn = 0; fn < 8; fn++)
                mx = fmaxf(mx, fmaxf(acc[fm][fn][half * 2], acc[fm][fn][half * 2 + 1]));
            float se = 0.0f;
            #pragma unroll
            for (int fn = 0; fn < 8; fn++)
                se += __expf(acc[fm][fn][half * 2] - mx)
                    + __expf(acc[fm][fn][half * 2 + 1] - mx);
            #pragma unroll
            for (int off = 1; off <= 2; off <<= 1) {
                float mo = __shfl_xor_sync(0xffffffffu, mx, off);
                float so = __shfl_xor_sync(0xffffffffu, se, off);
                float nm = fmaxf(mx, mo);
                se = se * __expf(mx - nm) + so * __expf(mo - nm);
                mx = nm;
            }
            if ((lane & 3) == 0) {
                int rloc = mr + fm * 16 + lr + half * 8;
                part[rloc * 4 + (wid >> 1)] = make_float2(mx, se);
            }
        }
    }
    __syncthreads();
    if (tid < 128) {
        float2 p0 = part[tid * 4 + 0];
        float2 p1 = part[tid * 4 + 1];
        float2 p2 = part[tid * 4 + 2];
        float2 p3 = part[tid * 4 + 3];
        float M = fmaxf(fmaxf(p0.x, p1.x), fmaxf(p2.x, p3.x));
        float S = p0.y * __expf(p0.x - M) + p1.y * __expf(p1.x - M)
                + p2.y * __expf(p2.x - M) + p3.y * __expf(p3.x - M);
        int mrow = (int)m0 + tid;
        int s = mrow >> 6, l = (mrow >> 3) & 7, b = mrow & 7;
        int o = (s * 8 + b) * 8 + l;
        g_part2[o * NTILES + blockIdx.y] = make_float2(M, S);
    }
}

// ---------------- small kernels ----------------
__global__ void gh_kernel(const float* __restrict__ h0, const float* __restrict__ whh,
                          const float* __restrict__ bhh)
{
    int i = blockIdx.x * 256 + threadIdx.x;
    if (i >= PB * D3) return;
    int b = i / D3, e = i % D3;
    float acc = bhh[e];
    const float4* hr = reinterpret_cast<const float4*>(h0 + b * PD);
    const float4* wr = reinterpret_cast<const float4*>(whh + (long long)e * PD);
    #pragma unroll 4
    for (int k = 0; k < PD / 4; k++) {
        float4 a = hr[k], w = wr[k];
        acc = fmaf(a.x, w.x, acc); acc = fmaf(a.y, w.y, acc);
        acc = fmaf(a.z, w.z, acc); acc = fmaf(a.w, w.w, acc);
    }
    g_gh[i] = acc;
}

__global__ void build_x(const float* __restrict__ emb, const float* __restrict__ slot,
                        const int* __restrict__ trg)
{
    int idx = blockIdx.x * 256 + threadIdx.x;
    int d = idx & (PD - 1);
    int m = idx >> 10;
    int s = m >> 6, l = (m >> 3) & 7, b = m & 7;
    float v;
    if (l == 0) v = slot[s * PD + d];
    else {
        int tok = trg[b * (PS * PL) + s * PL + (l - 1)];
        v = emb[(long long)tok * PD + d];
    }
    g_x[idx] = v;
    __nv_bfloat16 hi, lo; split2(v, hi, lo);
    g_A2x[m * 2048 + d] = hi;
    g_A2x[m * 2048 + 1024 + d] = lo;
}

__global__ void gru_kernel(const float* __restrict__ bih, const float* __restrict__ h0)
{
    int idx = blockIdx.x * 256 + threadIdx.x;
    int d = idx & (PD - 1);
    int m = idx >> 10;
    int b = m & 7;
    long long gb = (long long)m * D3;
    float ir = g_gi[gb + d]          + bih[d];
    float iz = g_gi[gb + PD + d]     + bih[PD + d];
    float in = g_gi[gb + 2 * PD + d] + bih[2 * PD + d];
    float hr = g_gh[b * D3 + d];
    float hz = g_gh[b * D3 + PD + d];
    float hn = g_gh[b * D3 + 2 * PD + d];
    float r = 1.0f / (1.0f + expf(-(ir + hr)));
    float z = 1.0f / (1.0f + expf(-(iz + hz)));
    float n = tanhf(in + r * hn);
    float h = (1.0f - z) * n + z * h0[b * PD + d];
    g_h[idx] = h;
    __nv_bfloat16 hi, lo; split2(h, hi, lo);
    g_A2h[m * 2048 + d] = hi;
    g_A2h[m * 2048 + 1024 + d] = lo;
}

__global__ void probs_kernel()
{
    int m = blockIdx.x;
    long long base = (long long)m * PT;
    int t = threadIdx.x;
    float v0 = g_scores[base + t];
    float v1 = g_scores[base + t + 256];
    float mx = blockMax(fmaxf(v0, v1));
    float e0 = __expf(v0 - mx), e1 = __expf(v1 - mx);
    float sum = blockSum(e0 + e1);
    float inv = 1.0f / sum;
    g_probs[base + t] = e0 * inv;
    g_probs[base + t + 256] = e1 * inv;
    __nv_bfloat16 h, lo;
    split2(v0, h, lo);
    g_S2[m * 1024 + t] = h; g_S2[m * 1024 + 512 + t] = lo;
    split2(v1, h, lo);
    g_S2[m * 1024 + t + 256] = h; g_S2[m * 1024 + 512 + t + 256] = lo;
}

__global__ void pgen_kernel(const float* __restrict__ w, const float* __restrict__ wb)
{
    int m = blockIdx.x;
    long long base = (long long)m * PD;
    float p = 0.0f;
    for (int d = threadIdx.x; d < PD; d += 256) {
        p = fmaf(g_h[base + d],   w[d],          p);
        p = fmaf(g_ctx[base + d], w[PD + d],     p);
        p = fmaf(g_x[base + d],   w[2 * PD + d], p);
    }
    p = blockSum(p);
    if (threadIdx.x == 0)
        g_pgen[m] = 1.0f / (1.0f + expf(-(p + wb[0])));
}

__global__ void combine_kernel()
{
    int o = blockIdx.x;
    int i = threadIdx.x;
    float M = -1e30f, S = 0.0f;
    if (i < NTILES) {
        float2 p = g_part2[o * NTILES + i];
        M = p.x; S = p.y;
    }
    __shared__ float smx[128], ssm[128];
    smx[i] = M; ssm[i] = S;
    __syncthreads();
    for (int st = 64; st; st >>= 1) {
        if (i < st) {
            float m1 = smx[i], s1 = ssm[i];
            float m2 = smx[i + st], s2 = ssm[i + st];
            float nm = fmaxf(m1, m2);
            smx[i] = nm;
            ssm[i] = s1 * __expf(m1 - nm) + s2 * __expf(m2 - nm);
        }
        __syncthreads();
    }
    if (i == 0) {
        int s = o >> 6, b = (o >> 3) & 7, l = o & 7;
        int m = s * 64 + l * 8 + b;
        float pg = g_pgen[m];
        g_rowMS[o] = make_float2(smx[0], pg / ssm[0]);
    }
}

__global__ void final_kernel(float* __restrict__ out, const int* __restrict__ story)
{
    int o = blockIdx.x;
    float2 ms = g_rowMS[o];
    long long base = (long long)o * PV;
    int s = o >> 6, b = (o >> 3) & 7, l = o & 7;
    int m = s * 64 + l * 8 + b;
    float4* dst = reinterpret_cast<float4*>(out + base);
    for (int i = threadIdx.x; i < PV / 4; i += 512) {
        float4 v = dst[i];
        v.x = __expf(v.x - ms.x) * ms.y;
        v.y = __expf(v.y - ms.x) * ms.y;
        v.z = __expf(v.z - ms.x) * ms.y;
        v.w = __expf(v.w - ms.x) * ms.y;
        dst[i] = v;
    }
    __syncthreads();
    float w = 1.0f - g_pgen[m];
    for (int t = threadIdx.x; t < PT; t += 512) {
        int tok = story[b * PT + t];
        atomicAdd(&out[base + tok], w * g_probs[(long long)m * PT + t]);
    }
}

__global__ void gate_kernel(float* __restrict__ out, const float* __restrict__ wg,
                            const float* __restrict__ bg)
{
    int o = blockIdx.x;
    int s = o / (PB * PG);
    int b = (o % (PB * PG)) / PG;
    int g = o % PG;
    int m = s * 64 + b;
    float p = 0.0f;
    for (int d = threadIdx.x; d < PD; d += 128)
        p = fmaf(g_ctx[(long long)m * PD + d], wg[g * PD + d], p);
    p = blockSum(p);
    if (threadIdx.x == 0) out[OUT_PTR_ELEMS + o] = p + bg[g];
}

// ---------------- launch ----------------
extern "C" void kernel_launch(void* const* d_in, const int* in_sizes, int n_in,
                              void* d_out, int out_size)
{
    const float* enc_h   = (const float*)d_in[0];
    const float* enc_out = (const float*)d_in[1];
    const int*   story   = (const int*)d_in[2];
    const int*   trg     = (const int*)d_in[3];
    const float* emb     = (const float*)d_in[4];
    const float* w_ih    = (const float*)d_in[5];
    const float* w_hh    = (const float*)d_in[6];
    const float* b_ih    = (const float*)d_in[7];
    const float* b_hh    = (const float*)d_in[8];
    const float* w_rw    = (const float*)d_in[9];
    const float* w_rb    = (const float*)d_in[10];
    const float* w_gw    = (const float*)d_in[11];
    const float* w_gb    = (const float*)d_in[12];
    const float* slot    = (const float*)d_in[13];
    float* out = (float*)d_out;

    float *pgi, *psc, *pcx;
    __nv_bfloat16 *pB2, *pA2h, *pA2x, *pW2, *pE2, *pET2, *pS2;
    cudaGetSymbolAddress((void**)&pgi,  g_gi);
    cudaGetSymbolAddress((void**)&psc,  g_scores);
    cudaGetSymbolAddress((void**)&pcx,  g_ctx);
    cudaGetSymbolAddress((void**)&pB2,  g_B2);
    cudaGetSymbolAddress((void**)&pA2h, g_A2h);
    cudaGetSymbolAddress((void**)&pA2x, g_A2x);
    cudaGetSymbolAddress((void**)&pW2,  g_W2);
    cudaGetSymbolAddress((void**)&pE2,  g_E2);
    cudaGetSymbolAddress((void**)&pET2, g_ET2);
    cudaGetSymbolAddress((void**)&pS2,  g_S2);

    cudaFuncSetAttribute(mma_gemm<false>, cudaFuncAttributeMaxDynamicSharedMemorySize, MMA_SMEM);
    cudaFuncSetAttribute(mma_gemm<true>,  cudaFuncAttributeMaxDynamicSharedMemorySize, MMA_SMEM);
    cudaFuncSetAttribute(mma_gemm_big,    cudaFuncAttributeMaxDynamicSharedMemorySize, BIG_SMEM);

    // zero split-K accumulation targets
    cudaMemsetAsync(pgi, 0, (size_t)SLB * D3 * 4);
    cudaMemsetAsync(psc, 0, (size_t)SLB * PT * 4);
    cudaMemsetAsync(pcx, 0, (size_t)SLB * PD * 4);

    // inputs + operand splits
    build_x<<<(SLB * PD) / 256, 256>>>(emb, slot, trg);
    split_generic<<<D3 * 128 / 256, 256>>>(w_ih, pW2, 10, (long long)D3 * 128);
    split_generic<<<PV * 128 / 256, 256>>>(emb, pB2, 10, (long long)PV * 128);

    // gi = x @ w_ih^T (M=1024, N=3072, K=1024), split-K=2
    mma_gemm<true><<<dim3(8, 24, 2), 128, MMA_SMEM>>>(
        pA2x, 2048, 0, pW2, 2048, 0, pgi, D3, 0, 1024, 2);

    // enc splits + gh
    split_generic<<<PB * PT * 128 / 256, 256>>>(enc_out, pE2, 10, (long long)PB * PT * 128);
    trans_split<<<dim3(PT / 32, PD / 32, PB), dim3(32, 8)>>>(enc_out, pET2);
    gh_kernel<<<(PB * D3 + 255) / 256, 256>>>(enc_h, w_hh, b_hh);

    // GRU -> h (+ split)
    gru_kernel<<<(SLB * PD) / 256, 256>>>(b_ih, enc_h);

    // scores = h . enc (per-b M=128, N=512, K=1024), split-K=4
    mma_gemm<true><<<dim3(1, 4, 32), 128, MMA_SMEM>>>(
        pA2h, 8 * 2048, 2048, pE2, 2048, (long long)PT * 2048,
        psc, 8 * 512, 512, 1024, 4);

    // probs (+ S2 split)
    probs_kernel<<<SLB, 256>>>();

    // context = scores @ enc (per-b M=128, N=1024, K=512), split-K=4
    mma_gemm<true><<<dim3(1, 8, 32), 128, MMA_SMEM>>>(
        pS2, 8 * 1024, 1024, pET2, 1024, (long long)PD * 1024,
        pcx, 8 * 1024, 1024, 512, 4);

    // p_gen
    pgen_kernel<<<SLB, 256>>>(w_rw, w_rb);

    // logits = h @ E^T (M=1024, N=32000, K=1024), 128x256 tiles, 4-stage
    mma_gemm_big<<<dim3(8, NTILES), 256, BIG_SMEM>>>(pA2h, pB2, out);

    // combine partials -> per-row (M, pg/S)
    combine_kernel<<<SLB, 128>>>();

    // scale + scatter
    final_kernel<<<SLB, 512>>>(out, story);

    // gate outputs
    gate_kernel<<<PS * PB * PG, 128>>>(out, w_gw, w_gb);
}

// round 15
// speedup vs baseline: 1.5627x; 1.0409x over previous
#include <cuda_runtime.h>
#include <cuda_bf16.h>
#include <math.h>
#include <stdint.h>

// Problem constants
#define PS   16
#define PB   8
#define PL   8
#define PV   32000
#define PD   1024
#define PT   512
#define PG   3
#define SLB  1024
#define D3   3072
#define NTILES 125            // PV / 256 (big-tile logits GEMM)
#define OUT_PTR_ELEMS 32768000LL

// ---------------- side stream for graph fork (created before mem baseline) ----------------
struct StreamInit {
    cudaStream_t s;
    cudaEvent_t e1, e2;
    StreamInit() {
        cudaStreamCreateWithFlags(&s, cudaStreamNonBlocking);
        cudaEventCreateWithFlags(&e1, cudaEventDisableTiming);
        cudaEventCreateWithFlags(&e2, cudaEventDisableTiming);
    }
};
static StreamInit g_si;

// ---------------- device scratch ----------------
__device__ float g_x[SLB * PD];
__device__ float g_h[SLB * PD];
__device__ float g_gi[SLB * D3];
__device__ float g_gh[PB * D3];
__device__ float g_scores[SLB * PT];
__device__ float g_probs[SLB * PT];
__device__ float g_ctx[SLB * PD];
__device__ float g_pgen[SLB];
__device__ float2 g_part2[SLB * NTILES];
__device__ float2 g_rowMS[SLB];
__device__ __nv_bfloat16 g_B2[(long long)PV * 2048];
__device__ __nv_bfloat16 g_A2h[SLB * 2048];
__device__ __nv_bfloat16 g_A2x[SLB * 2048];
__device__ __nv_bfloat16 g_W2[D3 * 2048];
__device__ __nv_bfloat16 g_E2[(long long)PB * PT * 2048];
__device__ __nv_bfloat16 g_ET2[(long long)PB * PD * 1024];
__device__ __nv_bfloat16 g_S2[SLB * 1024];

// ---------------- helpers ----------------
__device__ __forceinline__ uint32_t smem_u32(const void* p) {
    uint32_t a;
    asm("{ .reg .u64 t; cvta.to.shared.u64 t, %1; cvt.u32.u64 %0, t; }" : "=r"(a) : "l"(p));
    return a;
}
__device__ __forceinline__ void cp16(uint32_t s, const void* g) {
    asm volatile("cp.async.cg.shared.global [%0], [%1], 16;" :: "r"(s), "l"(g) : "memory");
}
__device__ __forceinline__ void cp_commit() {
    asm volatile("cp.async.commit_group;" ::: "memory");
}
template <int N>
__device__ __forceinline__ void cp_wait() {
    asm volatile("cp.async.wait_group %0;" :: "n"(N) : "memory");
}
__device__ __forceinline__ void mma16816(float& c0, float& c1, float& c2, float& c3,
                                         uint32_t a0, uint32_t a1, uint32_t a2, uint32_t a3,
                                         uint32_t b0, uint32_t b1) {
    asm volatile("mma.sync.aligned.m16n8k16.row.col.f32.bf16.bf16.f32 "
                 "{%0,%1,%2,%3}, {%4,%5,%6,%7}, {%8,%9}, {%0,%1,%2,%3};"
                 : "+f"(c0), "+f"(c1), "+f"(c2), "+f"(c3)
                 : "r"(a0), "r"(a1), "r"(a2), "r"(a3), "r"(b0), "r"(b1));
}
__device__ __forceinline__ void ldsm4(uint32_t& r0, uint32_t& r1, uint32_t& r2, uint32_t& r3,
                                      uint32_t addr) {
    asm volatile("ldmatrix.sync.aligned.m8n8.x4.shared.b16 {%0,%1,%2,%3}, [%4];"
                 : "=r"(r0), "=r"(r1), "=r"(r2), "=r"(r3) : "r"(addr));
}
__device__ __forceinline__ void split2(float v, __nv_bfloat16& hi, __nv_bfloat16& lo) {
    hi = __float2bfloat16(v);
    lo = __float2bfloat16(v - __bfloat162float(hi));
}
__device__ __forceinline__ uint32_t pack2(float a, float b) {
    __nv_bfloat162 t = __floats2bfloat162_rn(a, b);
    return *reinterpret_cast<uint32_t*>(&t);
}

// ---------------- reductions ----------------
__device__ __forceinline__ float warpMax(float v) {
    #pragma unroll
    for (int o = 16; o; o >>= 1) v = fmaxf(v, __shfl_xor_sync(0xffffffffu, v, o));
    return v;
}
__device__ __forceinline__ float warpSum(float v) {
    #pragma unroll
    for (int o = 16; o; o >>= 1) v += __shfl_xor_sync(0xffffffffu, v, o);
    return v;
}
__device__ float blockSum(float v) {
    __shared__ float sm[32];
    v = warpSum(v);
    int w = threadIdx.x >> 5, l = threadIdx.x & 31;
    __syncthreads();
    if (l == 0) sm[w] = v;
    __syncthreads();
    int nw = (blockDim.x + 31) >> 5;
    v = (threadIdx.x < nw) ? sm[threadIdx.x] : 0.0f;
    if (w == 0) v = warpSum(v);
    if (threadIdx.x == 0) sm[0] = v;
    __syncthreads();
    return sm[0];
}
__device__ float blockMax(float v) {
    __shared__ float sm[32];
    v = warpMax(v);
    int w = threadIdx.x >> 5, l = threadIdx.x & 31;
    __syncthreads();
    if (l == 0) sm[w] = v;
    __syncthreads();
    int nw = (blockDim.x + 31) >> 5;
    v = (threadIdx.x < nw) ? sm[threadIdx.x] : -INFINITY;
    if (w == 0) v = warpMax(v);
    if (threadIdx.x == 0) sm[0] = v;
    __syncthreads();
    return sm[0];
}

// ---------------- split kernels ----------------
__global__ void split_generic(const float* __restrict__ src, __nv_bfloat16* __restrict__ dst,
                              int kshift, long long total8)
{
    long long idx = (long long)blockIdx.x * 256 + threadIdx.x;
    if (idx >= total8) return;
    long long row = idx >> (kshift - 3);
    int c8 = (int)(idx & ((1 << (kshift - 3)) - 1));
    const float4* s4 = reinterpret_cast<const float4*>(src);
    float4 v0 = s4[idx * 2];
    float4 v1 = s4[idx * 2 + 1];
    uint4 uh, ul;
    uh.x = pack2(v0.x, v0.y);
    uh.y = pack2(v0.z, v0.w);
    uh.z = pack2(v1.x, v1.y);
    uh.w = pack2(v1.z, v1.w);
    float2 f;
    __nv_bfloat162 t;
    t = *reinterpret_cast<__nv_bfloat162*>(&uh.x); f = __bfloat1622float2(t);
    ul.x = pack2(v0.x - f.x, v0.y - f.y);
    t = *reinterpret_cast<__nv_bfloat162*>(&uh.y); f = __bfloat1622float2(t);
    ul.y = pack2(v0.z - f.x, v0.w - f.y);
    t = *reinterpret_cast<__nv_bfloat162*>(&uh.z); f = __bfloat1622float2(t);
    ul.z = pack2(v1.x - f.x, v1.y - f.y);
    t = *reinterpret_cast<__nv_bfloat162*>(&uh.w); f = __bfloat1622float2(t);
    ul.w = pack2(v1.z - f.x, v1.w - f.y);
    long long K = 1LL << kshift;
    __nv_bfloat16* dh = dst + row * 2 * K + (long long)c8 * 8;
    *reinterpret_cast<uint4*>(dh) = uh;
    *reinterpret_cast<uint4*>(dh + K) = ul;
}

__global__ void trans_split(const float* __restrict__ enc, __nv_bfloat16* __restrict__ dst)
{
    __shared__ float tile[32][33];
    int b = blockIdx.z;
    int d0 = blockIdx.y * 32;
    int t0 = blockIdx.x * 32;
    int tx = threadIdx.x, ty = threadIdx.y;
    const float* src = enc + ((long long)b * PT + t0) * PD + d0;
    #pragma unroll
    for (int j = 0; j < 4; j++)
        tile[ty + j * 8][tx] = src[(ty + j * 8) * PD + tx];
    __syncthreads();
    #pragma unroll
    for (int j = 0; j < 4; j++) {
        int d = d0 + ty + j * 8;
        float v = tile[tx][ty + j * 8];
        __nv_bfloat16 hi, lo; split2(v, hi, lo);
        long long ro = ((long long)(b << 10) + d) * 1024 + t0 + tx;
        dst[ro] = hi;
        dst[ro + 512] = lo;
    }
}

// ---------------- HMMA split GEMM: 128x128 tile, 4 warps, 2 CTA/SM ----------------
#define STAGE_B 32768
#define MMA_SMEM (3 * STAGE_B)

template <bool ATOMIC>
__global__ void __launch_bounds__(128, 2) mma_gemm(
    const __nv_bfloat16* __restrict__ A2, long long a_rs, long long a_batch,
    const __nv_bfloat16* __restrict__ B2, long long b_rs, long long b_batch,
    float* __restrict__ C, long long c_rs, long long c_batch,
    int Kfull, int ksplit)
{
    extern __shared__ char smd[];
    const uint32_t sbase = smem_u32(smd);
    const int tid = threadIdx.x;
    const int wid = tid >> 5;
    const int lane = tid & 31;
    const int lr = lane >> 2;
    const int mr = (wid & 1) * 64;
    const int nc = (wid >> 1) * 64;
    const long long m0 = (long long)blockIdx.x * 128;
    const long long n0 = (long long)blockIdx.y * 128;
    const int z = blockIdx.z / ksplit;
    const int ks = blockIdx.z % ksplit;
    const int Kp = Kfull / ksplit;
    const int CH = Kp >> 5;
    const int kbase = ks * Kp;
    const __nv_bfloat16* Ab = A2 + (long long)z * a_batch;
    const __nv_bfloat16* Bb = B2 + (long long)z * b_batch;

    const int g3 = lane >> 3;
    const int i8 = lane & 7;
    uint32_t PA[4], PBo[4];
    #pragma unroll
    for (int fm = 0; fm < 4; fm++) {
        uint32_t r = (uint32_t)(mr + fm * 16 + (g3 & 1) * 8 + i8);
        PA[fm] = (r * 64) ^ (((r >> 1) & 3) << 4) ^ ((uint32_t)(g3 >> 1) << 4);
    }
    #pragma unroll
    for (int fn2 = 0; fn2 < 4; fn2++) {
        uint32_t r = (uint32_t)(nc + fn2 * 16 + (g3 >> 1) * 8 + i8);
        PBo[fn2] = (r * 64) ^ (((r >> 1) & 3) << 4) ^ ((uint32_t)(g3 & 1) << 4);
    }

    float acc[4][8][4];
    #pragma unroll
    for (int i = 0; i < 4; i++)
        #pragma unroll
        for (int j = 0; j < 8; j++)
            #pragma unroll
            for (int k = 0; k < 4; k++) acc[i][j][k] = 0.0f;

    auto issue = [&](int c) {
        const int koff = kbase + (c << 5);
        const uint32_t st = sbase + (uint32_t)((c % 3) * STAGE_B);
        #pragma unroll
        for (int i = 0; i < 4; i++) {
            const int idx = tid + i * 128;
            const int r = idx >> 2, g = idx & 3;
            const uint32_t so = (uint32_t)(r * 64 + ((g ^ ((r >> 1) & 3)) << 4));
            const __nv_bfloat16* a = Ab + (m0 + r) * a_rs + koff + g * 8;
            cp16(st + so, a);
            cp16(st + 8192 + so, a + Kfull);
            const __nv_bfloat16* b = Bb + (n0 + r) * b_rs + koff + g * 8;
            cp16(st + 16384 + so, b);
            cp16(st + 24576 + so, b + Kfull);
        }
        cp_commit();
    };

    issue(0); issue(1);

    #pragma unroll 1
    for (int c = 0; c < CH; c++) {
        cp_wait<1>();
        __syncthreads();
        if (c + 2 < CH) issue(c + 2);

        const uint32_t st = sbase + (uint32_t)((c % 3) * STAGE_B);

        #pragma unroll
        for (int kc2 = 0; kc2 < 2; kc2++) {
            const uint32_t kx = (uint32_t)kc2 << 5;
            uint32_t ah[4][4], bh[8][2];
            #pragma unroll
            for (int fm = 0; fm < 4; fm++)
                ldsm4(ah[fm][0], ah[fm][1], ah[fm][2], ah[fm][3], st + (PA[fm] ^ kx));
            #pragma unroll
            for (int fn2 = 0; fn2 < 4; fn2++)
                ldsm4(bh[fn2 * 2][0], bh[fn2 * 2][1], bh[fn2 * 2 + 1][0], bh[fn2 * 2 + 1][1],
                      st + 16384 + (PBo[fn2] ^ kx));
            // pass 1: hi*hi
            #pragma unroll
            for (int fm = 0; fm < 4; fm++)
                #pragma unroll
                for (int fn = 0; fn < 8; fn++)
                    mma16816(acc[fm][fn][0], acc[fm][fn][1], acc[fm][fn][2], acc[fm][fn][3],
                             ah[fm][0], ah[fm][1], ah[fm][2], ah[fm][3], bh[fn][0], bh[fn][1]);
            // pass 2: lo*hi
            {
                uint32_t al[4][4];
                #pragma unroll
                for (int fm = 0; fm < 4; fm++)
                    ldsm4(al[fm][0], al[fm][1], al[fm][2], al[fm][3], st + 8192 + (PA[fm] ^ kx));
                #pragma unroll
                for (int fm = 0; fm < 4; fm++)
                    #pragma unroll
                    for (int fn = 0; fn < 8; fn++)
                        mma16816(acc[fm][fn][0], acc[fm][fn][1], acc[fm][fn][2], acc[fm][fn][3],
                                 al[fm][0], al[fm][1], al[fm][2], al[fm][3], bh[fn][0], bh[fn][1]);
            }
            // pass 3: hi*lo
            {
                uint32_t bl[8][2];
                #pragma unroll
                for (int fn2 = 0; fn2 < 4; fn2++)
                    ldsm4(bl[fn2 * 2][0], bl[fn2 * 2][1], bl[fn2 * 2 + 1][0], bl[fn2 * 2 + 1][1],
                          st + 24576 + (PBo[fn2] ^ kx));
                #pragma unroll
                for (int fm = 0; fm < 4; fm++)
                    #pragma unroll
                    for (int fn = 0; fn < 8; fn++)
                        mma16816(acc[fm][fn][0], acc[fm][fn][1], acc[fm][fn][2], acc[fm][fn][3],
                                 ah[fm][0], ah[fm][1], ah[fm][2], ah[fm][3], bl[fn][0], bl[fn][1]);
            }
        }
    }

    #pragma unroll
    for (int fm = 0; fm < 4; fm++) {
        const int mrow0 = (int)m0 + mr + fm * 16 + lr;
        const int mrow1 = mrow0 + 8;
        long long ro0 = (long long)z * c_batch + (long long)mrow0 * c_rs;
        long long ro1 = (long long)z * c_batch + (long long)mrow1 * c_rs;
        #pragma unroll
        for (int fn = 0; fn < 8; fn++) {
            const long long col = n0 + nc + fn * 8 + (lane & 3) * 2;
            if (ATOMIC) {
                atomicAdd(&C[ro0 + col],     acc[fm][fn][0]);
                atomicAdd(&C[ro0 + col + 1], acc[fm][fn][1]);
                atomicAdd(&C[ro1 + col],     acc[fm][fn][2]);
                atomicAdd(&C[ro1 + col + 1], acc[fm][fn][3]);
            } else {
                *reinterpret_cast<float2*>(C + ro0 + col) = make_float2(acc[fm][fn][0], acc[fm][fn][1]);
                *reinterpret_cast<float2*>(C + ro1 + col) = make_float2(acc[fm][fn][2], acc[fm][fn][3]);
            }
        }
    }
}

// ---------------- logits GEMM: 128x256 tile, 1 CTA/SM, 4-stage ----------------
#define BSTAGE_B 49152
#define BIG_SMEM (4 * BSTAGE_B)

__global__ void __launch_bounds__(256, 1) mma_gemm_big(
    const __nv_bfloat16* __restrict__ A2,   // [SLB][2048]
    const __nv_bfloat16* __restrict__ B2,   // [PV][2048]
    float* __restrict__ C)
{
    extern __shared__ char smd[];
    const uint32_t sbase = smem_u32(smd);
    const int tid = threadIdx.x;
    const int wid = tid >> 5;
    const int lane = tid & 31;
    const int lr = lane >> 2;
    const int mr = (wid & 1) * 64;
    const int nc = (wid >> 1) * 64;
    const long long m0 = (long long)blockIdx.x * 128;
    const long long n0 = (long long)blockIdx.y * 256;

    const int g3 = lane >> 3;
    const int i8 = lane & 7;
    uint32_t PA[4], PBo[4];
    #pragma unroll
    for (int fm = 0; fm < 4; fm++) {
        uint32_t r = (uint32_t)(mr + fm * 16 + (g3 & 1) * 8 + i8);
        PA[fm] = (r * 64) ^ (((r >> 1) & 3) << 4) ^ ((uint32_t)(g3 >> 1) << 4);
    }
    #pragma unroll
    for (int fn2 = 0; fn2 < 4; fn2++) {
        uint32_t r = (uint32_t)(nc + fn2 * 16 + (g3 >> 1) * 8 + i8);
        PBo[fn2] = (r * 64) ^ (((r >> 1) & 3) << 4) ^ ((uint32_t)(g3 & 1) << 4);
    }

    float acc[4][8][4];
    #pragma unroll
    for (int i = 0; i < 4; i++)
        #pragma unroll
        for (int j = 0; j < 8; j++)
            #pragma unroll
            for (int k = 0; k < 4; k++) acc[i][j][k] = 0.0f;

    auto issue = [&](int c) {
        const int koff = c << 5;
        const uint32_t st = sbase + (uint32_t)((c & 3) * BSTAGE_B);
        #pragma unroll
        for (int i = 0; i < 2; i++) {
            const int idx = tid + i * 256;
            const int r = idx >> 2, g = idx & 3;
            const uint32_t so = (uint32_t)(r * 64 + ((g ^ ((r >> 1) & 3)) << 4));
            const __nv_bfloat16* a = A2 + (m0 + r) * 2048 + koff + g * 8;
            cp16(st + so, a);
            cp16(st + 8192 + so, a + 1024);
        }
        #pragma unroll
        for (int i = 0; i < 4; i++) {
            const int idx = tid + i * 256;
            const int r = idx >> 2, g = idx & 3;
            const uint32_t so = (uint32_t)(r * 64 + ((g ^ ((r >> 1) & 3)) << 4));
            const __nv_bfloat16* b = B2 + (n0 + r) * 2048 + koff + g * 8;
            cp16(st + 16384 + so, b);
            cp16(st + 32768 + so, b + 1024);
        }
        cp_commit();
    };

    issue(0); issue(1); issue(2);

    #pragma unroll 1
    for (int c = 0; c < 32; c++) {
        cp_wait<2>();
        __syncthreads();
        if (c + 3 < 32) issue(c + 3);

        const uint32_t st = sbase + (uint32_t)((c & 3) * BSTAGE_B);

        #pragma unroll
        for (int kc2 = 0; kc2 < 2; kc2++) {
            const uint32_t kx = (uint32_t)kc2 << 5;
            uint32_t ah[4][4], bh[8][2];
            #pragma unroll
            for (int fm = 0; fm < 4; fm++)
                ldsm4(ah[fm][0], ah[fm][1], ah[fm][2], ah[fm][3], st + (PA[fm] ^ kx));
            #pragma unroll
            for (int fn2 = 0; fn2 < 4; fn2++)
                ldsm4(bh[fn2 * 2][0], bh[fn2 * 2][1], bh[fn2 * 2 + 1][0], bh[fn2 * 2 + 1][1],
                      st + 16384 + (PBo[fn2] ^ kx));
            // hi * hi
            #pragma unroll
            for (int fm = 0; fm < 4; fm++)
                #pragma unroll
                for (int fn = 0; fn < 8; fn++)
                    mma16816(acc[fm][fn][0], acc[fm][fn][1], acc[fm][fn][2], acc[fm][fn][3],
                             ah[fm][0], ah[fm][1], ah[fm][2], ah[fm][3], bh[fn][0], bh[fn][1]);
            // lo * hi
            {
                uint32_t al[4][4];
                #pragma unroll
                for (int fm = 0; fm < 4; fm++)
                    ldsm4(al[fm][0], al[fm][1], al[fm][2], al[fm][3], st + 8192 + (PA[fm] ^ kx));
                #pragma unroll
                for (int fm = 0; fm < 4; fm++)
                    #pragma unroll
                    for (int fn = 0; fn < 8; fn++)
                        mma16816(acc[fm][fn][0], acc[fm][fn][1], acc[fm][fn][2], acc[fm][fn][3],
                                 al[fm][0], al[fm][1], al[fm][2], al[fm][3], bh[fn][0], bh[fn][1]);
            }
            // hi * lo
            {
                uint32_t bl[8][2];
                #pragma unroll
                for (int fn2 = 0; fn2 < 4; fn2++)
                    ldsm4(bl[fn2 * 2][0], bl[fn2 * 2][1], bl[fn2 * 2 + 1][0], bl[fn2 * 2 + 1][1],
                          st + 32768 + (PBo[fn2] ^ kx));
                #pragma unroll
                for (int fm = 0; fm < 4; fm++)
                    #pragma unroll
                    for (int fn = 0; fn < 8; fn++)
                        mma16816(acc[fm][fn][0], acc[fm][fn][1], acc[fm][fn][2], acc[fm][fn][3],
                                 ah[fm][0], ah[fm][1], ah[fm][2], ah[fm][3], bl[fn][0], bl[fn][1]);
            }
        }
    }

    // store permuted + softmax partials
    #pragma unroll
    for (int fm = 0; fm < 4; fm++) {
        const int mrow0 = (int)m0 + mr + fm * 16 + lr;
        const int mrow1 = mrow0 + 8;
        int s0 = mrow0 >> 6, l0 = (mrow0 >> 3) & 7, b0 = mrow0 & 7;
        int s1 = mrow1 >> 6, l1 = (mrow1 >> 3) & 7, b1 = mrow1 & 7;
        long long ro0 = (long long)((s0 * 8 + b0) * 8 + l0) * (long long)PV;
        long long ro1 = (long long)((s1 * 8 + b1) * 8 + l1) * (long long)PV;
        #pragma unroll
        for (int fn = 0; fn < 8; fn++) {
            const long long col = n0 + nc + fn * 8 + (lane & 3) * 2;
            *reinterpret_cast<float2*>(C + ro0 + col) = make_float2(acc[fm][fn][0], acc[fm][fn][1]);
            *reinterpret_cast<float2*>(C + ro1 + col) = make_float2(acc[fm][fn][2], acc[fm][fn][3]);
        }
    }

    cp_wait<0>();
    __syncthreads();
    float2* part = reinterpret_cast<float2*>(smd);   // [128][4]
    #pragma unroll
    for (int fm = 0; fm < 4; fm++) {
        #pragma unroll
        for (int half = 0; half < 2; half++) {
            float mx = -1e30f;
            #pragma unroll
            for (int fn = 0; fn < 8; fn++)
                mx = fmaxf(mx, fmaxf(acc[fm][fn][half * 2], acc[fm][fn][half * 2 + 1]));
            float se = 0.0f;
            #pragma unroll
            for (int fn = 0; fn < 8; fn++)
                se += __expf(acc[fm][fn][half * 2] - mx)
                    + __expf(acc[fm][fn][half * 2 + 1] - mx);
            #pragma unroll
            for (int off = 1; off <= 2; off <<= 1) {
                float mo = __shfl_xor_sync(0xffffffffu, mx, off);
                float so = __shfl_xor_sync(0xffffffffu, se, off);
                float nm = fmaxf(mx, mo);
                se = se * __expf(mx - nm) + so * __expf(mo - nm);
                mx = nm;
            }
            if ((lane & 3) == 0) {
                int rloc = mr + fm * 16 + lr + half * 8;
                part[rloc * 4 + (wid >> 1)] = make_float2(mx, se);
            }
        }
    }
    __syncthreads();
    if (tid < 128) {
        float2 p0 = part[tid * 4 + 0];
        float2 p1 = part[tid * 4 + 1];
        float2 p2 = part[tid * 4 + 2];
        float2 p3 = part[tid * 4 + 3];
        float M = fmaxf(fmaxf(p0.x, p1.x), fmaxf(p2.x, p3.x));
        float S = p0.y * __expf(p0.x - M) + p1.y * __expf(p1.x - M)
                + p2.y * __expf(p2.x - M) + p3.y * __expf(p3.x - M);
        int mrow = (int)m0 + tid;
        int s = mrow >> 6, l = (mrow >> 3) & 7, b = mrow & 7;
        int o = (s * 8 + b) * 8 + l;
        g_part2[o * NTILES + blockIdx.y] = make_float2(M, S);
    }
}

// ---------------- small kernels ----------------
__global__ void gh_kernel(const float* __restrict__ h0, const float* __restrict__ whh,
                          const float* __restrict__ bhh)
{
    int i = blockIdx.x * 256 + threadIdx.x;
    if (i >= PB * D3) return;
    int b = i / D3, e = i % D3;
    float acc = bhh[e];
    const float4* hr = reinterpret_cast<const float4*>(h0 + b * PD);
    const float4* wr = reinterpret_cast<const float4*>(whh + (long long)e * PD);
    #pragma unroll 4
    for (int k = 0; k < PD / 4; k++) {
        float4 a = hr[k], w = wr[k];
        acc = fmaf(a.x, w.x, acc); acc = fmaf(a.y, w.y, acc);
        acc = fmaf(a.z, w.z, acc); acc = fmaf(a.w, w.w, acc);
    }
    g_gh[i] = acc;
}

__global__ void build_x(const float* __restrict__ emb, const float* __restrict__ slot,
                        const int* __restrict__ trg)
{
    int idx = blockIdx.x * 256 + threadIdx.x;
    int d = idx & (PD - 1);
    int m = idx >> 10;
    int s = m >> 6, l = (m >> 3) & 7, b = m & 7;
    float v;
    if (l == 0) v = slot[s * PD + d];
    else {
        int tok = trg[b * (PS * PL) + s * PL + (l - 1)];
        v = emb[(long long)tok * PD + d];
    }
    g_x[idx] = v;
    __nv_bfloat16 hi, lo; split2(v, hi, lo);
    g_A2x[m * 2048 + d] = hi;
    g_A2x[m * 2048 + 1024 + d] = lo;
}

__global__ void gru_kernel(const float* __restrict__ bih, const float* __restrict__ h0)
{
    int idx = blockIdx.x * 256 + threadIdx.x;
    int d = idx & (PD - 1);
    int m = idx >> 10;
    int b = m & 7;
    long long gb = (long long)m * D3;
    float ir = g_gi[gb + d]          + bih[d];
    float iz = g_gi[gb + PD + d]     + bih[PD + d];
    float in = g_gi[gb + 2 * PD + d] + bih[2 * PD + d];
    float hr = g_gh[b * D3 + d];
    float hz = g_gh[b * D3 + PD + d];
    float hn = g_gh[b * D3 + 2 * PD + d];
    float r = 1.0f / (1.0f + expf(-(ir + hr)));
    float z = 1.0f / (1.0f + expf(-(iz + hz)));
    float n = tanhf(in + r * hn);
    float h = (1.0f - z) * n + z * h0[b * PD + d];
    g_h[idx] = h;
    __nv_bfloat16 hi, lo; split2(h, hi, lo);
    g_A2h[m * 2048 + d] = hi;
    g_A2h[m * 2048 + 1024 + d] = lo;
}

__global__ void probs_kernel()
{
    int m = blockIdx.x;
    long long base = (long long)m * PT;
    int t = threadIdx.x;
    float v0 = g_scores[base + t];
    float v1 = g_scores[base + t + 256];
    float mx = blockMax(fmaxf(v0, v1));
    float e0 = __expf(v0 - mx), e1 = __expf(v1 - mx);
    float sum = blockSum(e0 + e1);
    float inv = 1.0f / sum;
    g_probs[base + t] = e0 * inv;
    g_probs[base + t + 256] = e1 * inv;
    __nv_bfloat16 h, lo;
    split2(v0, h, lo);
    g_S2[m * 1024 + t] = h; g_S2[m * 1024 + 512 + t] = lo;
    split2(v1, h, lo);
    g_S2[m * 1024 + t + 256] = h; g_S2[m * 1024 + 512 + t + 256] = lo;
}

__global__ void pgen_kernel(const float* __restrict__ w, const float* __restrict__ wb)
{
    int m = blockIdx.x;
    long long base = (long long)m * PD;
    float p = 0.0f;
    for (int d = threadIdx.x; d < PD; d += 256) {
        p = fmaf(g_h[base + d],   w[d],          p);
        p = fmaf(g_ctx[base + d], w[PD + d],     p);
        p = fmaf(g_x[base + d],   w[2 * PD + d], p);
    }
    p = blockSum(p);
    if (threadIdx.x == 0)
        g_pgen[m] = 1.0f / (1.0f + expf(-(p + wb[0])));
}

__global__ void combine_kernel()
{
    int o = blockIdx.x;
    int i = threadIdx.x;
    float M = -1e30f, S = 0.0f;
    if (i < NTILES) {
        float2 p = g_part2[o * NTILES + i];
        M = p.x; S = p.y;
    }
    __shared__ float smx[128], ssm[128];
    smx[i] = M; ssm[i] = S;
    __syncthreads();
    for (int st = 64; st; st >>= 1) {
        if (i < st) {
            float m1 = smx[i], s1 = ssm[i];
            float m2 = smx[i + st], s2 = ssm[i + st];
            float nm = fmaxf(m1, m2);
            smx[i] = nm;
            ssm[i] = s1 * __expf(m1 - nm) + s2 * __expf(m2 - nm);
        }
        __syncthreads();
    }
    if (i == 0) {
        int s = o >> 6, b = (o >> 3) & 7, l = o & 7;
        int m = s * 64 + l * 8 + b;
        float pg = g_pgen[m];
        g_rowMS[o] = make_float2(smx[0], pg / ssm[0]);
    }
}

__global__ void final_kernel(float* __restrict__ out, const int* __restrict__ story)
{
    int o = blockIdx.x;
    float2 ms = g_rowMS[o];
    long long base = (long long)o * PV;
    int s = o >> 6, b = (o >> 3) & 7, l = o & 7;
    int m = s * 64 + l * 8 + b;
    float4* dst = reinterpret_cast<float4*>(out + base);
    for (int i = threadIdx.x; i < PV / 4; i += 512) {
        float4 v = dst[i];
        v.x = __expf(v.x - ms.x) * ms.y;
        v.y = __expf(v.y - ms.x) * ms.y;
        v.z = __expf(v.z - ms.x) * ms.y;
        v.w = __expf(v.w - ms.x) * ms.y;
        dst[i] = v;
    }
    __syncthreads();
    float w = 1.0f - g_pgen[m];
    for (int t = threadIdx.x; t < PT; t += 512) {
        int tok = story[b * PT + t];
        atomicAdd(&out[base + tok], w * g_probs[(long long)m * PT + t]);
    }
}

__global__ void gate_kernel(float* __restrict__ out, const float* __restrict__ wg,
                            const float* __restrict__ bg)
{
    int o = blockIdx.x;
    int s = o / (PB * PG);
    int b = (o % (PB * PG)) / PG;
    int g = o % PG;
    int m = s * 64 + b;
    float p = 0.0f;
    for (int d = threadIdx.x; d < PD; d += 128)
        p = fmaf(g_ctx[(long long)m * PD + d], wg[g * PD + d], p);
    p = blockSum(p);
    if (threadIdx.x == 0) out[OUT_PTR_ELEMS + o] = p + bg[g];
}

// ---------------- launch ----------------
extern "C" void kernel_launch(void* const* d_in, const int* in_sizes, int n_in,
                              void* d_out, int out_size)
{
    const float* enc_h   = (const float*)d_in[0];
    const float* enc_out = (const float*)d_in[1];
    const int*   story   = (const int*)d_in[2];
    const int*   trg     = (const int*)d_in[3];
    const float* emb     = (const float*)d_in[4];
    const float* w_ih    = (const float*)d_in[5];
    const float* w_hh    = (const float*)d_in[6];
    const float* b_ih    = (const float*)d_in[7];
    const float* b_hh    = (const float*)d_in[8];
    const float* w_rw    = (const float*)d_in[9];
    const float* w_rb    = (const float*)d_in[10];
    const float* w_gw    = (const float*)d_in[11];
    const float* w_gb    = (const float*)d_in[12];
    const float* slot    = (const float*)d_in[13];
    float* out = (float*)d_out;

    float *pgi, *psc, *pcx;
    __nv_bfloat16 *pB2, *pA2h, *pA2x, *pW2, *pE2, *pET2, *pS2;
    cudaGetSymbolAddress((void**)&pgi,  g_gi);
    cudaGetSymbolAddress((void**)&psc,  g_scores);
    cudaGetSymbolAddress((void**)&pcx,  g_ctx);
    cudaGetSymbolAddress((void**)&pB2,  g_B2);
    cudaGetSymbolAddress((void**)&pA2h, g_A2h);
    cudaGetSymbolAddress((void**)&pA2x, g_A2x);
    cudaGetSymbolAddress((void**)&pW2,  g_W2);
    cudaGetSymbolAddress((void**)&pE2,  g_E2);
    cudaGetSymbolAddress((void**)&pET2, g_ET2);
    cudaGetSymbolAddress((void**)&pS2,  g_S2);

    cudaFuncSetAttribute(mma_gemm<false>, cudaFuncAttributeMaxDynamicSharedMemorySize, MMA_SMEM);
    cudaFuncSetAttribute(mma_gemm<true>,  cudaFuncAttributeMaxDynamicSharedMemorySize, MMA_SMEM);
    cudaFuncSetAttribute(mma_gemm_big,    cudaFuncAttributeMaxDynamicSharedMemorySize, BIG_SMEM);

    // zero split-K accumulation targets
    cudaMemsetAsync(pgi, 0, (size_t)SLB * D3 * 4);
    cudaMemsetAsync(psc, 0, (size_t)SLB * PT * 4);
    cudaMemsetAsync(pcx, 0, (size_t)SLB * PD * 4);

    // inputs + operand splits
    build_x<<<(SLB * PD) / 256, 256>>>(emb, slot, trg);
    split_generic<<<D3 * 128 / 256, 256>>>(w_ih, pW2, 10, (long long)D3 * 128);
    split_generic<<<PV * 128 / 256, 256>>>(emb, pB2, 10, (long long)PV * 128);

    // gi = x @ w_ih^T (M=1024, N=3072, K=1024), split-K=2
    mma_gemm<true><<<dim3(8, 24, 2), 128, MMA_SMEM>>>(
        pA2x, 2048, 0, pW2, 2048, 0, pgi, D3, 0, 1024, 2);

    // enc splits + gh
    split_generic<<<PB * PT * 128 / 256, 256>>>(enc_out, pE2, 10, (long long)PB * PT * 128);
    trans_split<<<dim3(PT / 32, PD / 32, PB), dim3(32, 8)>>>(enc_out, pET2);
    gh_kernel<<<(PB * D3 + 255) / 256, 256>>>(enc_h, w_hh, b_hh);

    // GRU -> h (+ split)
    gru_kernel<<<(SLB * PD) / 256, 256>>>(b_ih, enc_h);

    // ---- graph fork: attention chain on side stream, logits GEMM on main ----
    cudaEventRecord(g_si.e1, 0);
    cudaStreamWaitEvent(g_si.s, g_si.e1, 0);

    // side stream: scores -> probs -> context -> pgen -> gate
    mma_gemm<true><<<dim3(1, 4, 32), 128, MMA_SMEM, g_si.s>>>(
        pA2h, 8 * 2048, 2048, pE2, 2048, (long long)PT * 2048,
        psc, 8 * 512, 512, 1024, 4);
    probs_kernel<<<SLB, 256, 0, g_si.s>>>();
    mma_gemm<true><<<dim3(1, 8, 32), 128, MMA_SMEM, g_si.s>>>(
        pS2, 8 * 1024, 1024, pET2, 1024, (long long)PD * 1024,
        pcx, 8 * 1024, 1024, 512, 4);
    pgen_kernel<<<SLB, 256, 0, g_si.s>>>(w_rw, w_rb);
    gate_kernel<<<PS * PB * PG, 128, 0, g_si.s>>>(out, w_gw, w_gb);
    cudaEventRecord(g_si.e2, g_si.s);

    // main stream: logits = h @ E^T (M=1024, N=32000, K=1024)
    mma_gemm_big<<<dim3(8, NTILES), 256, BIG_SMEM>>>(pA2h, pB2, out);

    // join
    cudaStreamWaitEvent(0, g_si.e2, 0);

    // combine partials -> per-row (M, pg/S)
    combine_kernel<<<SLB, 128>>>();

    // scale + scatter
    final_kernel<<<SLB, 512>>>(out, story);
}

// round 17
// speedup vs baseline: 1.6047x; 1.0269x over previous
#include <cuda_runtime.h>
#include <cuda_bf16.h>
#include <math.h>
#include <stdint.h>

// Problem constants
#define PS   16
#define PB   8
#define PL   8
#define PV   32000
#define PD   1024
#define PT   512
#define PG   3
#define SLB  1024
#define D3   3072
#define NTILES 125            // PV / 256 (big-tile logits GEMM)
#define OUT_PTR_ELEMS 32768000LL

// ---------------- side stream for graph fork (created before mem baseline) ----------------
struct StreamInit {
    cudaStream_t s;
    cudaEvent_t e0, e1, e2, eB2;
    StreamInit() {
        cudaStreamCreateWithFlags(&s, cudaStreamNonBlocking);
        cudaEventCreateWithFlags(&e0, cudaEventDisableTiming);
        cudaEventCreateWithFlags(&e1, cudaEventDisableTiming);
        cudaEventCreateWithFlags(&e2, cudaEventDisableTiming);
        cudaEventCreateWithFlags(&eB2, cudaEventDisableTiming);
    }
};
static StreamInit g_si;

// ---------------- device scratch ----------------
__device__ float g_x[SLB * PD];
__device__ float g_h[SLB * PD];
__device__ float g_gi[SLB * D3];
__device__ float g_gh[PB * D3];
__device__ float g_scores[SLB * PT];
__device__ float g_probs[SLB * PT];
__device__ float g_ctx[SLB * PD];
__device__ float g_pgen[SLB];
__device__ float2 g_part2[SLB * NTILES];
__device__ float2 g_rowMS[SLB];
__device__ __nv_bfloat16 g_B2[(long long)PV * 2048];
__device__ __nv_bfloat16 g_A2h[SLB * 2048];
__device__ __nv_bfloat16 g_A2x[SLB * 2048];
__device__ __nv_bfloat16 g_W2[D3 * 2048];
__device__ __nv_bfloat16 g_E2[(long long)PB * PT * 2048];
__device__ __nv_bfloat16 g_ET2[(long long)PB * PD * 1024];
__device__ __nv_bfloat16 g_S2[SLB * 1024];

// ---------------- helpers ----------------
__device__ __forceinline__ uint32_t smem_u32(const void* p) {
    uint32_t a;
    asm("{ .reg .u64 t; cvta.to.shared.u64 t, %1; cvt.u32.u64 %0, t; }" : "=r"(a) : "l"(p));
    return a;
}
__device__ __forceinline__ void cp16(uint32_t s, const void* g) {
    asm volatile("cp.async.cg.shared.global [%0], [%1], 16;" :: "r"(s), "l"(g) : "memory");
}
__device__ __forceinline__ void cp_commit() {
    asm volatile("cp.async.commit_group;" ::: "memory");
}
template <int N>
__device__ __forceinline__ void cp_wait() {
    asm volatile("cp.async.wait_group %0;" :: "n"(N) : "memory");
}
__device__ __forceinline__ void mma16816(float& c0, float& c1, float& c2, float& c3,
                                         uint32_t a0, uint32_t a1, uint32_t a2, uint32_t a3,
                                         uint32_t b0, uint32_t b1) {
    asm volatile("mma.sync.aligned.m16n8k16.row.col.f32.bf16.bf16.f32 "
                 "{%0,%1,%2,%3}, {%4,%5,%6,%7}, {%8,%9}, {%0,%1,%2,%3};"
                 : "+f"(c0), "+f"(c1), "+f"(c2), "+f"(c3)
                 : "r"(a0), "r"(a1), "r"(a2), "r"(a3), "r"(b0), "r"(b1));
}
__device__ __forceinline__ void ldsm4(uint32_t& r0, uint32_t& r1, uint32_t& r2, uint32_t& r3,
                                      uint32_t addr) {
    asm volatile("ldmatrix.sync.aligned.m8n8.x4.shared.b16 {%0,%1,%2,%3}, [%4];"
                 : "=r"(r0), "=r"(r1), "=r"(r2), "=r"(r3) : "r"(addr));
}
__device__ __forceinline__ void split2(float v, __nv_bfloat16& hi, __nv_bfloat16& lo) {
    hi = __float2bfloat16(v);
    lo = __float2bfloat16(v - __bfloat162float(hi));
}
__device__ __forceinline__ uint32_t pack2(float a, float b) {
    __nv_bfloat162 t = __floats2bfloat162_rn(a, b);
    return *reinterpret_cast<uint32_t*>(&t);
}

// ---------------- reductions ----------------
__device__ __forceinline__ float warpMax(float v) {
    #pragma unroll
    for (int o = 16; o; o >>= 1) v = fmaxf(v, __shfl_xor_sync(0xffffffffu, v, o));
    return v;
}
__device__ __forceinline__ float warpSum(float v) {
    #pragma unroll
    for (int o = 16; o; o >>= 1) v += __shfl_xor_sync(0xffffffffu, v, o);
    return v;
}
__device__ float blockSum(float v) {
    __shared__ float sm[32];
    v = warpSum(v);
    int w = threadIdx.x >> 5, l = threadIdx.x & 31;
    __syncthreads();
    if (l == 0) sm[w] = v;
    __syncthreads();
    int nw = (blockDim.x + 31) >> 5;
    v = (threadIdx.x < nw) ? sm[threadIdx.x] : 0.0f;
    if (w == 0) v = warpSum(v);
    if (threadIdx.x == 0) sm[0] = v;
    __syncthreads();
    return sm[0];
}
__device__ float blockMax(float v) {
    __shared__ float sm[32];
    v = warpMax(v);
    int w = threadIdx.x >> 5, l = threadIdx.x & 31;
    __syncthreads();
    if (l == 0) sm[w] = v;
    __syncthreads();
    int nw = (blockDim.x + 31) >> 5;
    v = (threadIdx.x < nw) ? sm[threadIdx.x] : -INFINITY;
    if (w == 0) v = warpMax(v);
    if (threadIdx.x == 0) sm[0] = v;
    __syncthreads();
    return sm[0];
}

// ---------------- split kernels ----------------
__global__ void split_generic(const float* __restrict__ src, __nv_bfloat16* __restrict__ dst,
                              int kshift, long long total8)
{
    long long idx = (long long)blockIdx.x * 256 + threadIdx.x;
    if (idx >= total8) return;
    long long row = idx >> (kshift - 3);
    int c8 = (int)(idx & ((1 << (kshift - 3)) - 1));
    const float4* s4 = reinterpret_cast<const float4*>(src);
    float4 v0 = s4[idx * 2];
    float4 v1 = s4[idx * 2 + 1];
    uint4 uh, ul;
    uh.x = pack2(v0.x, v0.y);
    uh.y = pack2(v0.z, v0.w);
    uh.z = pack2(v1.x, v1.y);
    uh.w = pack2(v1.z, v1.w);
    float2 f;
    __nv_bfloat162 t;
    t = *reinterpret_cast<__nv_bfloat162*>(&uh.x); f = __bfloat1622float2(t);
    ul.x = pack2(v0.x - f.x, v0.y - f.y);
    t = *reinterpret_cast<__nv_bfloat162*>(&uh.y); f = __bfloat1622float2(t);
    ul.y = pack2(v0.z - f.x, v0.w - f.y);
    t = *reinterpret_cast<__nv_bfloat162*>(&uh.z); f = __bfloat1622float2(t);
    ul.z = pack2(v1.x - f.x, v1.y - f.y);
    t = *reinterpret_cast<__nv_bfloat162*>(&uh.w); f = __bfloat1622float2(t);
    ul.w = pack2(v1.z - f.x, v1.w - f.y);
    long long K = 1LL << kshift;
    __nv_bfloat16* dh = dst + row * 2 * K + (long long)c8 * 8;
    *reinterpret_cast<uint4*>(dh) = uh;
    *reinterpret_cast<uint4*>(dh + K) = ul;
}

__global__ void trans_split(const float* __restrict__ enc, __nv_bfloat16* __restrict__ dst)
{
    __shared__ float tile[32][33];
    int b = blockIdx.z;
    int d0 = blockIdx.y * 32;
    int t0 = blockIdx.x * 32;
    int tx = threadIdx.x, ty = threadIdx.y;
    const float* src = enc + ((long long)b * PT + t0) * PD + d0;
    #pragma unroll
    for (int j = 0; j < 4; j++)
        tile[ty + j * 8][tx] = src[(ty + j * 8) * PD + tx];
    __syncthreads();
    #pragma unroll
    for (int j = 0; j < 4; j++) {
        int d = d0 + ty + j * 8;
        float v = tile[tx][ty + j * 8];
        __nv_bfloat16 hi, lo; split2(v, hi, lo);
        long long ro = ((long long)(b << 10) + d) * 1024 + t0 + tx;
        dst[ro] = hi;
        dst[ro + 512] = lo;
    }
}

// ---------------- HMMA split GEMM: 128x128 tile, 4 warps, 2 CTA/SM ----------------
#define STAGE_B 32768
#define MMA_SMEM (3 * STAGE_B)

template <bool ATOMIC>
__global__ void __launch_bounds__(128, 2) mma_gemm(
    const __nv_bfloat16* __restrict__ A2, long long a_rs, long long a_batch,
    const __nv_bfloat16* __restrict__ B2, long long b_rs, long long b_batch,
    float* __restrict__ C, long long c_rs, long long c_batch,
    int Kfull, int ksplit)
{
    extern __shared__ char smd[];
    const uint32_t sbase = smem_u32(smd);
    const int tid = threadIdx.x;
    const int wid = tid >> 5;
    const int lane = tid & 31;
    const int lr = lane >> 2;
    const int mr = (wid & 1) * 64;
    const int nc = (wid >> 1) * 64;
    const long long m0 = (long long)blockIdx.x * 128;
    const long long n0 = (long long)blockIdx.y * 128;
    const int z = blockIdx.z / ksplit;
    const int ks = blockIdx.z % ksplit;
    const int Kp = Kfull / ksplit;
    const int CH = Kp >> 5;
    const int kbase = ks * Kp;
    const __nv_bfloat16* Ab = A2 + (long long)z * a_batch;
    const __nv_bfloat16* Bb = B2 + (long long)z * b_batch;

    const int g3 = lane >> 3;
    const int i8 = lane & 7;
    uint32_t PA[4], PBo[4];
    #pragma unroll
    for (int fm = 0; fm < 4; fm++) {
        uint32_t r = (uint32_t)(mr + fm * 16 + (g3 & 1) * 8 + i8);
        PA[fm] = (r * 64) ^ (((r >> 1) & 3) << 4) ^ ((uint32_t)(g3 >> 1) << 4);
    }
    #pragma unroll
    for (int fn2 = 0; fn2 < 4; fn2++) {
        uint32_t r = (uint32_t)(nc + fn2 * 16 + (g3 >> 1) * 8 + i8);
        PBo[fn2] = (r * 64) ^ (((r >> 1) & 3) << 4) ^ ((uint32_t)(g3 & 1) << 4);
    }

    float acc[4][8][4];
    #pragma unroll
    for (int i = 0; i < 4; i++)
        #pragma unroll
        for (int j = 0; j < 8; j++)
            #pragma unroll
            for (int k = 0; k < 4; k++) acc[i][j][k] = 0.0f;

    auto issue = [&](int c) {
        const int koff = kbase + (c << 5);
        const uint32_t st = sbase + (uint32_t)((c % 3) * STAGE_B);
        #pragma unroll
        for (int i = 0; i < 4; i++) {
            const int idx = tid + i * 128;
            const int r = idx >> 2, g = idx & 3;
            const uint32_t so = (uint32_t)(r * 64 + ((g ^ ((r >> 1) & 3)) << 4));
            const __nv_bfloat16* a = Ab + (m0 + r) * a_rs + koff + g * 8;
            cp16(st + so, a);
            cp16(st + 8192 + so, a + Kfull);
            const __nv_bfloat16* b = Bb + (n0 + r) * b_rs + koff + g * 8;
            cp16(st + 16384 + so, b);
            cp16(st + 24576 + so, b + Kfull);
        }
        cp_commit();
    };

    issue(0); issue(1);

    #pragma unroll 1
    for (int c = 0; c < CH; c++) {
        cp_wait<1>();
        __syncthreads();
        if (c + 2 < CH) issue(c + 2);

        const uint32_t st = sbase + (uint32_t)((c % 3) * STAGE_B);

        #pragma unroll
        for (int kc2 = 0; kc2 < 2; kc2++) {
            const uint32_t kx = (uint32_t)kc2 << 5;
            uint32_t ah[4][4], bh[8][2];
            #pragma unroll
            for (int fm = 0; fm < 4; fm++)
                ldsm4(ah[fm][0], ah[fm][1], ah[fm][2], ah[fm][3], st + (PA[fm] ^ kx));
            #pragma unroll
            for (int fn2 = 0; fn2 < 4; fn2++)
                ldsm4(bh[fn2 * 2][0], bh[fn2 * 2][1], bh[fn2 * 2 + 1][0], bh[fn2 * 2 + 1][1],
                      st + 16384 + (PBo[fn2] ^ kx));
            // pass 1: hi*hi
            #pragma unroll
            for (int fm = 0; fm < 4; fm++)
                #pragma unroll
                for (int fn = 0; fn < 8; fn++)
                    mma16816(acc[fm][fn][0], acc[fm][fn][1], acc[fm][fn][2], acc[fm][fn][3],
                             ah[fm][0], ah[fm][1], ah[fm][2], ah[fm][3], bh[fn][0], bh[fn][1]);
            // pass 2: lo*hi
            {
                uint32_t al[4][4];
                #pragma unroll
                for (int fm = 0; fm < 4; fm++)
                    ldsm4(al[fm][0], al[fm][1], al[fm][2], al[fm][3], st + 8192 + (PA[fm] ^ kx));
                #pragma unroll
                for (int fm = 0; fm < 4; fm++)
                    #pragma unroll
                    for (int fn = 0; fn < 8; fn++)
                        mma16816(acc[fm][fn][0], acc[fm][fn][1], acc[fm][fn][2], acc[fm][fn][3],
                                 al[fm][0], al[fm][1], al[fm][2], al[fm][3], bh[fn][0], bh[fn][1]);
            }
            // pass 3: hi*lo
            {
                uint32_t bl[8][2];
                #pragma unroll
                for (int fn2 = 0; fn2 < 4; fn2++)
                    ldsm4(bl[fn2 * 2][0], bl[fn2 * 2][1], bl[fn2 * 2 + 1][0], bl[fn2 * 2 + 1][1],
                          st + 24576 + (PBo[fn2] ^ kx));
                #pragma unroll
                for (int fm = 0; fm < 4; fm++)
                    #pragma unroll
                    for (int fn = 0; fn < 8; fn++)
                        mma16816(acc[fm][fn][0], acc[fm][fn][1], acc[fm][fn][2], acc[fm][fn][3],
                                 ah[fm][0], ah[fm][1], ah[fm][2], ah[fm][3], bl[fn][0], bl[fn][1]);
            }
        }
    }

    #pragma unroll
    for (int fm = 0; fm < 4; fm++) {
        const int mrow0 = (int)m0 + mr + fm * 16 + lr;
        const int mrow1 = mrow0 + 8;
        long long ro0 = (long long)z * c_batch + (long long)mrow0 * c_rs;
        long long ro1 = (long long)z * c_batch + (long long)mrow1 * c_rs;
        #pragma unroll
        for (int fn = 0; fn < 8; fn++) {
            const long long col = n0 + nc + fn * 8 + (lane & 3) * 2;
            if (ATOMIC) {
                atomicAdd(&C[ro0 + col],     acc[fm][fn][0]);
                atomicAdd(&C[ro0 + col + 1], acc[fm][fn][1]);
                atomicAdd(&C[ro1 + col],     acc[fm][fn][2]);
                atomicAdd(&C[ro1 + col + 1], acc[fm][fn][3]);
            } else {
                *reinterpret_cast<float2*>(C + ro0 + col) = make_float2(acc[fm][fn][0], acc[fm][fn][1]);
                *reinterpret_cast<float2*>(C + ro1 + col) = make_float2(acc[fm][fn][2], acc[fm][fn][3]);
            }
        }
    }
}

// ---------------- logits GEMM: 128x256 tile, 1 CTA/SM, 4-stage ----------------
#define BSTAGE_B 49152
#define BIG_SMEM (4 * BSTAGE_B)

__global__ void __launch_bounds__(256, 1) mma_gemm_big(
    const __nv_bfloat16* __restrict__ A2,   // [SLB][2048]
    const __nv_bfloat16* __restrict__ B2,   // [PV][2048]
    float* __restrict__ C)
{
    extern __shared__ char smd[];
    const uint32_t sbase = smem_u32(smd);
    const int tid = threadIdx.x;
    const int wid = tid >> 5;
    const int lane = tid & 31;
    const int lr = lane >> 2;
    const int mr = (wid & 1) * 64;
    const int nc = (wid >> 1) * 64;
    const long long m0 = (long long)blockIdx.x * 128;
    const long long n0 = (long long)blockIdx.y * 256;

    const int g3 = lane >> 3;
    const int i8 = lane & 7;
    uint32_t PA[4], PBo[4];
    #pragma unroll
    for (int fm = 0; fm < 4; fm++) {
        uint32_t r = (uint32_t)(mr + fm * 16 + (g3 & 1) * 8 + i8);
        PA[fm] = (r * 64) ^ (((r >> 1) & 3) << 4) ^ ((uint32_t)(g3 >> 1) << 4);
    }
    #pragma unroll
    for (int fn2 = 0; fn2 < 4; fn2++) {
        uint32_t r = (uint32_t)(nc + fn2 * 16 + (g3 >> 1) * 8 + i8);
        PBo[fn2] = (r * 64) ^ (((r >> 1) & 3) << 4) ^ ((uint32_t)(g3 & 1) << 4);
    }

    float acc[4][8][4];
    #pragma unroll
    for (int i = 0; i < 4; i++)
        #pragma unroll
        for (int j = 0; j < 8; j++)
            #pragma unroll
            for (int k = 0; k < 4; k++) acc[i][j][k] = 0.0f;

    auto issue = [&](int c) {
        const int koff = c << 5;
        const uint32_t st = sbase + (uint32_t)((c & 3) * BSTAGE_B);
        #pragma unroll
        for (int i = 0; i < 2; i++) {
            const int idx = tid + i * 256;
            const int r = idx >> 2, g = idx & 3;
            const uint32_t so = (uint32_t)(r * 64 + ((g ^ ((r >> 1) & 3)) << 4));
            const __nv_bfloat16* a = A2 + (m0 + r) * 2048 + koff + g * 8;
            cp16(st + so, a);
            cp16(st + 8192 + so, a + 1024);
        }
        #pragma unroll
        for (int i = 0; i < 4; i++) {
            const int idx = tid + i * 256;
            const int r = idx >> 2, g = idx & 3;
            const uint32_t so = (uint32_t)(r * 64 + ((g ^ ((r >> 1) & 3)) << 4));
            const __nv_bfloat16* b = B2 + (n0 + r) * 2048 + koff + g * 8;
            cp16(st + 16384 + so, b);
            cp16(st + 32768 + so, b + 1024);
        }
        cp_commit();
    };

    issue(0); issue(1); issue(2);

    #pragma unroll 1
    for (int c = 0; c < 32; c++) {
        cp_wait<2>();
        __syncthreads();
        if (c + 3 < 32) issue(c + 3);

        const uint32_t st = sbase + (uint32_t)((c & 3) * BSTAGE_B);

        #pragma unroll
        for (int kc2 = 0; kc2 < 2; kc2++) {
            const uint32_t kx = (uint32_t)kc2 << 5;
            uint32_t ah[4][4], bh[8][2];
            #pragma unroll
            for (int fm = 0; fm < 4; fm++)
                ldsm4(ah[fm][0], ah[fm][1], ah[fm][2], ah[fm][3], st + (PA[fm] ^ kx));
            #pragma unroll
            for (int fn2 = 0; fn2 < 4; fn2++)
                ldsm4(bh[fn2 * 2][0], bh[fn2 * 2][1], bh[fn2 * 2 + 1][0], bh[fn2 * 2 + 1][1],
                      st + 16384 + (PBo[fn2] ^ kx));
            // hi * hi
            #pragma unroll
            for (int fm = 0; fm < 4; fm++)
                #pragma unroll
                for (int fn = 0; fn < 8; fn++)
                    mma16816(acc[fm][fn][0], acc[fm][fn][1], acc[fm][fn][2], acc[fm][fn][3],
                             ah[fm][0], ah[fm][1], ah[fm][2], ah[fm][3], bh[fn][0], bh[fn][1]);
            // lo * hi
            {
                uint32_t al[4][4];
                #pragma unroll
                for (int fm = 0; fm < 4; fm++)
                    ldsm4(al[fm][0], al[fm][1], al[fm][2], al[fm][3], st + 8192 + (PA[fm] ^ kx));
                #pragma unroll
                for (int fm = 0; fm < 4; fm++)
                    #pragma unroll
                    for (int fn = 0; fn < 8; fn++)
                        mma16816(acc[fm][fn][0], acc[fm][fn][1], acc[fm][fn][2], acc[fm][fn][3],
                                 al[fm][0], al[fm][1], al[fm][2], al[fm][3], bh[fn][0], bh[fn][1]);
            }
            // hi * lo
            {
                uint32_t bl[8][2];
                #pragma unroll
                for (int fn2 = 0; fn2 < 4; fn2++)
                    ldsm4(bl[fn2 * 2][0], bl[fn2 * 2][1], bl[fn2 * 2 + 1][0], bl[fn2 * 2 + 1][1],
                          st + 32768 + (PBo[fn2] ^ kx));
                #pragma unroll
                for (int fm = 0; fm < 4; fm++)
                    #pragma unroll
                    for (int fn = 0; fn < 8; fn++)
                        mma16816(acc[fm][fn][0], acc[fm][fn][1], acc[fm][fn][2], acc[fm][fn][3],
                                 ah[fm][0], ah[fm][1], ah[fm][2], ah[fm][3], bl[fn][0], bl[fn][1]);
            }
        }
    }

    // store permuted + softmax partials
    #pragma unroll
    for (int fm = 0; fm < 4; fm++) {
        const int mrow0 = (int)m0 + mr + fm * 16 + lr;
        const int mrow1 = mrow0 + 8;
        int s0 = mrow0 >> 6, l0 = (mrow0 >> 3) & 7, b0 = mrow0 & 7;
        int s1 = mrow1 >> 6, l1 = (mrow1 >> 3) & 7, b1 = mrow1 & 7;
        long long ro0 = (long long)((s0 * 8 + b0) * 8 + l0) * (long long)PV;
        long long ro1 = (long long)((s1 * 8 + b1) * 8 + l1) * (long long)PV;
        #pragma unroll
        for (int fn = 0; fn < 8; fn++) {
            const long long col = n0 + nc + fn * 8 + (lane & 3) * 2;
            *reinterpret_cast<float2*>(C + ro0 + col) = make_float2(acc[fm][fn][0], acc[fm][fn][1]);
            *reinterpret_cast<float2*>(C + ro1 + col) = make_float2(acc[fm][fn][2], acc[fm][fn][3]);
        }
    }

    cp_wait<0>();
    __syncthreads();
    float2* part = reinterpret_cast<float2*>(smd);   // [128][4]
    #pragma unroll
    for (int fm = 0; fm < 4; fm++) {
        #pragma unroll
        for (int half = 0; half < 2; half++) {
            float mx = -1e30f;
            #pragma unroll
            for (int fn = 0; fn < 8; fn++)
                mx = fmaxf(mx, fmaxf(acc[fm][fn][half * 2], acc[fm][fn][half * 2 + 1]));
            float se = 0.0f;
            #pragma unroll
            for (int fn = 0; fn < 8; fn++)
                se += __expf(acc[fm][fn][half * 2] - mx)
                    + __expf(acc[fm][fn][half * 2 + 1] - mx);
            #pragma unroll
            for (int off = 1; off <= 2; off <<= 1) {
                float mo = __shfl_xor_sync(0xffffffffu, mx, off);
                float so = __shfl_xor_sync(0xffffffffu, se, off);
                float nm = fmaxf(mx, mo);
                se = se * __expf(mx - nm) + so * __expf(mo - nm);
                mx = nm;
            }
            if ((lane & 3) == 0) {
                int rloc = mr + fm * 16 + lr + half * 8;
                part[rloc * 4 + (wid >> 1)] = make_float2(mx, se);
            }
        }
    }
    __syncthreads();
    if (tid < 128) {
        float2 p0 = part[tid * 4 + 0];
        float2 p1 = part[tid * 4 + 1];
        float2 p2 = part[tid * 4 + 2];
        float2 p3 = part[tid * 4 + 3];
        float M = fmaxf(fmaxf(p0.x, p1.x), fmaxf(p2.x, p3.x));
        float S = p0.y * __expf(p0.x - M) + p1.y * __expf(p1.x - M)
                + p2.y * __expf(p2.x - M) + p3.y * __expf(p3.x - M);
        int mrow = (int)m0 + tid;
        int s = mrow >> 6, l = (mrow >> 3) & 7, b = mrow & 7;
        int o = (s * 8 + b) * 8 + l;
        g_part2[o * NTILES + blockIdx.y] = make_float2(M, S);
    }
}

// ---------------- small kernels ----------------
__global__ void gh_kernel(const float* __restrict__ h0, const float* __restrict__ whh,
                          const float* __restrict__ bhh)
{
    int i = blockIdx.x * 256 + threadIdx.x;
    if (i >= PB * D3) return;
    int b = i / D3, e = i % D3;
    float acc = bhh[e];
    const float4* hr = reinterpret_cast<const float4*>(h0 + b * PD);
    const float4* wr = reinterpret_cast<const float4*>(whh + (long long)e * PD);
    #pragma unroll 4
    for (int k = 0; k < PD / 4; k++) {
        float4 a = hr[k], w = wr[k];
        acc = fmaf(a.x, w.x, acc); acc = fmaf(a.y, w.y, acc);
        acc = fmaf(a.z, w.z, acc); acc = fmaf(a.w, w.w, acc);
    }
    g_gh[i] = acc;
}

__global__ void build_x(const float* __restrict__ emb, const float* __restrict__ slot,
                        const int* __restrict__ trg)
{
    int idx = blockIdx.x * 256 + threadIdx.x;
    int d = idx & (PD - 1);
    int m = idx >> 10;
    int s = m >> 6, l = (m >> 3) & 7, b = m & 7;
    float v;
    if (l == 0) v = slot[s * PD + d];
    else {
        int tok = trg[b * (PS * PL) + s * PL + (l - 1)];
        v = emb[(long long)tok * PD + d];
    }
    g_x[idx] = v;
    __nv_bfloat16 hi, lo; split2(v, hi, lo);
    g_A2x[m * 2048 + d] = hi;
    g_A2x[m * 2048 + 1024 + d] = lo;
}

__global__ void gru_kernel(const float* __restrict__ bih, const float* __restrict__ h0)
{
    int idx = blockIdx.x * 256 + threadIdx.x;
    int d = idx & (PD - 1);
    int m = idx >> 10;
    int b = m & 7;
    long long gb = (long long)m * D3;
    float ir = g_gi[gb + d]          + bih[d];
    float iz = g_gi[gb + PD + d]     + bih[PD + d];
    float in = g_gi[gb + 2 * PD + d] + bih[2 * PD + d];
    float hr = g_gh[b * D3 + d];
    float hz = g_gh[b * D3 + PD + d];
    float hn = g_gh[b * D3 + 2 * PD + d];
    float r = 1.0f / (1.0f + expf(-(ir + hr)));
    float z = 1.0f / (1.0f + expf(-(iz + hz)));
    float n = tanhf(in + r * hn);
    float h = (1.0f - z) * n + z * h0[b * PD + d];
    g_h[idx] = h;
    __nv_bfloat16 hi, lo; split2(h, hi, lo);
    g_A2h[m * 2048 + d] = hi;
    g_A2h[m * 2048 + 1024 + d] = lo;
}

__global__ void probs_kernel()
{
    int m = blockIdx.x;
    long long base = (long long)m * PT;
    int t = threadIdx.x;
    float v0 = g_scores[base + t];
    float v1 = g_scores[base + t + 256];
    float mx = blockMax(fmaxf(v0, v1));
    float e0 = __expf(v0 - mx), e1 = __expf(v1 - mx);
    float sum = blockSum(e0 + e1);
    float inv = 1.0f / sum;
    g_probs[base + t] = e0 * inv;
    g_probs[base + t + 256] = e1 * inv;
    __nv_bfloat16 h, lo;
    split2(v0, h, lo);
    g_S2[m * 1024 + t] = h; g_S2[m * 1024 + 512 + t] = lo;
    split2(v1, h, lo);
    g_S2[m * 1024 + t + 256] = h; g_S2[m * 1024 + 512 + t + 256] = lo;
}

__global__ void pgen_kernel(const float* __restrict__ w, const float* __restrict__ wb)
{
    int m = blockIdx.x;
    long long base = (long long)m * PD;
    float p = 0.0f;
    for (int d = threadIdx.x; d < PD; d += 256) {
        p = fmaf(g_h[base + d],   w[d],          p);
        p = fmaf(g_ctx[base + d], w[PD + d],     p);
        p = fmaf(g_x[base + d],   w[2 * PD + d], p);
    }
    p = blockSum(p);
    if (threadIdx.x == 0)
        g_pgen[m] = 1.0f / (1.0f + expf(-(p + wb[0])));
}

__global__ void combine_kernel()
{
    int o = blockIdx.x;
    int i = threadIdx.x;
    float M = -1e30f, S = 0.0f;
    if (i < NTILES) {
        float2 p = g_part2[o * NTILES + i];
        M = p.x; S = p.y;
    }
    __shared__ float smx[128], ssm[128];
    smx[i] = M; ssm[i] = S;
    __syncthreads();
    for (int st = 64; st; st >>= 1) {
        if (i < st) {
            float m1 = smx[i], s1 = ssm[i];
            float m2 = smx[i + st], s2 = ssm[i + st];
            float nm = fmaxf(m1, m2);
            smx[i] = nm;
            ssm[i] = s1 * __expf(m1 - nm) + s2 * __expf(m2 - nm);
        }
        __syncthreads();
    }
    if (i == 0) {
        int s = o >> 6, b = (o >> 3) & 7, l = o & 7;
        int m = s * 64 + l * 8 + b;
        float pg = g_pgen[m];
        g_rowMS[o] = make_float2(smx[0], pg / ssm[0]);
    }
}

__global__ void final_kernel(float* __restrict__ out, const int* __restrict__ story)
{
    int o = blockIdx.x;
    float2 ms = g_rowMS[o];
    long long base = (long long)o * PV;
    int s = o >> 6, b = (o >> 3) & 7, l = o & 7;
    int m = s * 64 + l * 8 + b;
    float4* dst = reinterpret_cast<float4*>(out + base);
    for (int i = threadIdx.x; i < PV / 4; i += 512) {
        float4 v = dst[i];
        v.x = __expf(v.x - ms.x) * ms.y;
        v.y = __expf(v.y - ms.x) * ms.y;
        v.z = __expf(v.z - ms.x) * ms.y;
        v.w = __expf(v.w - ms.x) * ms.y;
        dst[i] = v;
    }
    __syncthreads();
    float w = 1.0f - g_pgen[m];
    for (int t = threadIdx.x; t < PT; t += 512) {
        int tok = story[b * PT + t];
        atomicAdd(&out[base + tok], w * g_probs[(long long)m * PT + t]);
    }
}

__global__ void gate_kernel(float* __restrict__ out, const float* __restrict__ wg,
                            const float* __restrict__ bg)
{
    int o = blockIdx.x;
    int s = o / (PB * PG);
    int b = (o % (PB * PG)) / PG;
    int g = o % PG;
    int m = s * 64 + b;
    float p = 0.0f;
    for (int d = threadIdx.x; d < PD; d += 128)
        p = fmaf(g_ctx[(long long)m * PD + d], wg[g * PD + d], p);
    p = blockSum(p);
    if (threadIdx.x == 0) out[OUT_PTR_ELEMS + o] = p + bg[g];
}

// ---------------- launch ----------------
extern "C" void kernel_launch(void* const* d_in, const int* in_sizes, int n_in,
                              void* d_out, int out_size)
{
    const float* enc_h   = (const float*)d_in[0];
    const float* enc_out = (const float*)d_in[1];
    const int*   story   = (const int*)d_in[2];
    const int*   trg     = (const int*)d_in[3];
    const float* emb     = (const float*)d_in[4];
    const float* w_ih    = (const float*)d_in[5];
    const float* w_hh    = (const float*)d_in[6];
    const float* b_ih    = (const float*)d_in[7];
    const float* b_hh    = (const float*)d_in[8];
    const float* w_rw    = (const float*)d_in[9];
    const float* w_rb    = (const float*)d_in[10];
    const float* w_gw    = (const float*)d_in[11];
    const float* w_gb    = (const float*)d_in[12];
    const float* slot    = (const float*)d_in[13];
    float* out = (float*)d_out;

    float *pgi, *psc, *pcx;
    __nv_bfloat16 *pB2, *pA2h, *pA2x, *pW2, *pE2, *pET2, *pS2;
    cudaGetSymbolAddress((void**)&pgi,  g_gi);
    cudaGetSymbolAddress((void**)&psc,  g_scores);
    cudaGetSymbolAddress((void**)&pcx,  g_ctx);
    cudaGetSymbolAddress((void**)&pB2,  g_B2);
    cudaGetSymbolAddress((void**)&pA2h, g_A2h);
    cudaGetSymbolAddress((void**)&pA2x, g_A2x);
    cudaGetSymbolAddress((void**)&pW2,  g_W2);
    cudaGetSymbolAddress((void**)&pE2,  g_E2);
    cudaGetSymbolAddress((void**)&pET2, g_ET2);
    cudaGetSymbolAddress((void**)&pS2,  g_S2);

    cudaFuncSetAttribute(mma_gemm<false>, cudaFuncAttributeMaxDynamicSharedMemorySize, MMA_SMEM);
    cudaFuncSetAttribute(mma_gemm<true>,  cudaFuncAttributeMaxDynamicSharedMemorySize, MMA_SMEM);
    cudaFuncSetAttribute(mma_gemm_big,    cudaFuncAttributeMaxDynamicSharedMemorySize, BIG_SMEM);

    // ---- legal capture fork: side stream joins via event from origin stream ----
    cudaEventRecord(g_si.e0, 0);
    cudaStreamWaitEvent(g_si.s, g_si.e0, 0);

    // side stream: B2 split (needed only by logits GEMM), then enc splits
    split_generic<<<PV * 128 / 256, 256, 0, g_si.s>>>(emb, pB2, 10, (long long)PV * 128);
    cudaEventRecord(g_si.eB2, g_si.s);
    split_generic<<<PB * PT * 128 / 256, 256, 0, g_si.s>>>(enc_out, pE2, 10, (long long)PB * PT * 128);
    trans_split<<<dim3(PT / 32, PD / 32, PB), dim3(32, 8), 0, g_si.s>>>(enc_out, pET2);

    // main stream: GRU path
    cudaMemsetAsync(pgi, 0, (size_t)SLB * D3 * 4);
    cudaMemsetAsync(psc, 0, (size_t)SLB * PT * 4);
    cudaMemsetAsync(pcx, 0, (size_t)SLB * PD * 4);

    build_x<<<(SLB * PD) / 256, 256>>>(emb, slot, trg);
    split_generic<<<D3 * 128 / 256, 256>>>(w_ih, pW2, 10, (long long)D3 * 128);
    gh_kernel<<<(PB * D3 + 255) / 256, 256>>>(enc_h, w_hh, b_hh);

    // gi = x @ w_ih^T (M=1024, N=3072, K=1024), split-K=2
    mma_gemm<true><<<dim3(8, 24, 2), 128, MMA_SMEM>>>(
        pA2x, 2048, 0, pW2, 2048, 0, pgi, D3, 0, 1024, 2);

    // GRU -> h (+ split)
    gru_kernel<<<(SLB * PD) / 256, 256>>>(b_ih, enc_h);

    // fork: attention chain continues on side stream after h is ready
    cudaEventRecord(g_si.e1, 0);
    cudaStreamWaitEvent(g_si.s, g_si.e1, 0);

    mma_gemm<true><<<dim3(1, 4, 32), 128, MMA_SMEM, g_si.s>>>(
        pA2h, 8 * 2048, 2048, pE2, 2048, (long long)PT * 2048,
        psc, 8 * 512, 512, 1024, 4);
    probs_kernel<<<SLB, 256, 0, g_si.s>>>();
    mma_gemm<true><<<dim3(1, 8, 32), 128, MMA_SMEM, g_si.s>>>(
        pS2, 8 * 1024, 1024, pET2, 1024, (long long)PD * 1024,
        pcx, 8 * 1024, 1024, 512, 4);
    pgen_kernel<<<SLB, 256, 0, g_si.s>>>(w_rw, w_rb);
    gate_kernel<<<PS * PB * PG, 128, 0, g_si.s>>>(out, w_gw, w_gb);
    cudaEventRecord(g_si.e2, g_si.s);

    // main stream: logits = h @ E^T (needs B2 from side stream)
    cudaStreamWaitEvent(0, g_si.eB2, 0);
    mma_gemm_big<<<dim3(8, NTILES), 256, BIG_SMEM>>>(pA2h, pB2, out);

    // join
    cudaStreamWaitEvent(0, g_si.e2, 0);

    // combine partials -> per-row (M, pg/S)
    combine_kernel<<<SLB, 128>>>();

    // scale + scatter
    final_kernel<<<SLB, 512>>>(out, story);
}